// round 5
// baseline (speedup 1.0000x reference)
#include <cuda_runtime.h>

#define LATENT 16
#define HID 512
#define DD 64
#define NB 128
#define NG 128
#define OUTSZ 12610
#define OUTSZ_PAD 12612

// Scratch (device globals — no allocation allowed)
__device__ float g_h0[NB * HID];
__device__ float g_h1[NB * HID];
__device__ float g_wb[NB * OUTSZ_PAD];   // stored PRE-PERMUTED into decoder layout

typedef unsigned long long u64;

__device__ __forceinline__ u64 pack2(float lo, float hi) {
    u64 r; asm("mov.b64 %0, {%1, %2};" : "=l"(r) : "f"(lo), "f"(hi)); return r;
}
__device__ __forceinline__ void unpack2(u64 v, float& lo, float& hi) {
    asm("mov.b64 {%0, %1}, %2;" : "=f"(lo), "=f"(hi) : "l"(v));
}
// packed fp32 FMA: d = a*b + d  (2 fp32 lanes per instruction)
__device__ __forceinline__ void fma2(u64& d, u64 a, u64 b) {
    asm("fma.rn.f32x2 %0, %1, %2, %0;" : "+l"(d) : "l"(a), "l"(b));
}

__device__ __forceinline__ float leaky(float x) { return x > 0.0f ? x : 0.01f * x; }

// fast sin: 2-step Cody-Waite range reduction + MUFU sin (args stay < ~40)
__device__ __forceinline__ float fsin(float x) {
    float k = rintf(x * 0.15915494309189535f);
    x = fmaf(k, -6.28125f, x);
    x = fmaf(k, -1.9353071795864769e-3f, x);
    return __sinf(x);
}

// Decoder smem layout offsets (floats), produced by the permuted GEMM epilogue:
//  W1 [0,4096) W2 [4096,8192) W3 [8192,12288) W0 [12288,12352)
//  b1 [12352,12416) b2 [12416,12480) b3 [12480,12544)
//  W4 [12544,12608)  b0 [12608]  b4 [12609]
#define OFF_W0 12288
#define OFF_B  12352
#define OFF_W4 12544

__device__ __forceinline__ int perm_wb(int n) {
    if (n < 4161)  return (n < 64) ? 12288 + n : (n == 64 ? 12608 : n - 65);
    if (n < 8321)  return (n < 4225) ? 12352 + (n - 4161) : 4096 + (n - 4225);
    if (n < 12481) return (n < 8385) ? 12416 + (n - 8321) : 8192 + (n - 8385);
    if (n < 12545) return 12480 + (n - 12481);
    return (n < 12609) ? 12544 + (n - 12545) : 12609;
}

// ---------------------------------------------------------------------------
// Kernel 1: h0 = leaky_relu(z @ hw0 + hb0)    (128 x 512, K=16)
// ---------------------------------------------------------------------------
__global__ void k_h0(const float* __restrict__ z, const float* __restrict__ hw0,
                     const float* __restrict__ hb0) {
    int b = blockIdx.x;
    int j = threadIdx.x;
    const float* zr = z + b * LATENT;
    float acc = hb0[j];
#pragma unroll
    for (int k = 0; k < LATENT; k++) acc = fmaf(zr[k], hw0[k * HID + j], acc);
    g_h0[b * HID + j] = leaky(acc);
}

// ---------------------------------------------------------------------------
// Tiled fp32 GEMM, packed f32x2 FMA.
//  - A smem tile stored DUPLICATED as u64 (v,v) -> rap is one broadcast LDS.64
//  - B fragments strided (tx*2 + j*32) -> warp LDS.64 covers 128 contiguous B
//  - optional column permutation on store (PERM) for the decoder layout
// ---------------------------------------------------------------------------
template <int BM, int BN, int BK, int NT, int ACT, int PERM>
__global__ void __launch_bounds__(NT)
gemm_bias(const float* __restrict__ A, const float* __restrict__ B,
          const float* __restrict__ bias, float* __restrict__ C,
          int M, int N, int K, int ldc) {
    constexpr int TY = NT / 16;
    constexpr int TM = BM / TY;
    constexpr int TNH = BN / 32;   // u64 accumulator columns per thread
    __shared__ __align__(16) u64 As[BK][BM];     // duplicated A
    __shared__ __align__(16) float Bs[BK][BN];

    int tid = threadIdx.x;
    int tx = tid & 15, ty = tid >> 4;
    int m0 = blockIdx.y * BM, n0 = blockIdx.x * BN;

    u64 acc[TM][TNH];
#pragma unroll
    for (int i = 0; i < TM; i++)
#pragma unroll
        for (int j = 0; j < TNH; j++) acc[i][j] = pack2(0.0f, 0.0f);

    for (int k0 = 0; k0 < K; k0 += BK) {
        // A tile: float4 along K, store duplicated & transposed
#pragma unroll
        for (int idx = tid; idx < BM * BK / 4; idx += NT) {
            int r = idx / (BK / 4), c4 = idx % (BK / 4);
            float4 v = *(const float4*)&A[(size_t)(m0 + r) * K + k0 + c4 * 4];
            As[c4 * 4 + 0][r] = pack2(v.x, v.x);
            As[c4 * 4 + 1][r] = pack2(v.y, v.y);
            As[c4 * 4 + 2][r] = pack2(v.z, v.z);
            As[c4 * 4 + 3][r] = pack2(v.w, v.w);
        }
        // B tile: scalar coalesced, guarded
#pragma unroll
        for (int idx = tid; idx < BK * BN; idx += NT) {
            int r = idx / BN, c = idx % BN;
            int n = n0 + c;
            Bs[r][c] = (n < N) ? B[(size_t)(k0 + r) * N + n] : 0.0f;
        }
        __syncthreads();
#pragma unroll
        for (int k = 0; k < BK; k++) {
            u64 rap[TM], rbp[TNH];
#pragma unroll
            for (int i = 0; i < TM; i++) rap[i] = As[k][ty * TM + i];
#pragma unroll
            for (int j = 0; j < TNH; j++)
                rbp[j] = *(const u64*)&Bs[k][tx * 2 + j * 32];
#pragma unroll
            for (int i = 0; i < TM; i++)
#pragma unroll
                for (int j = 0; j < TNH; j++) fma2(acc[i][j], rap[i], rbp[j]);
        }
        __syncthreads();
    }

#pragma unroll
    for (int i = 0; i < TM; i++) {
        int m = m0 + ty * TM + i;
#pragma unroll
        for (int j = 0; j < TNH; j++) {
            float lo, hi;
            unpack2(acc[i][j], lo, hi);
            int n = n0 + tx * 2 + j * 32;
            if (n < N) {
                float v = lo + bias[n];
                if (ACT) v = leaky(v);
                C[(size_t)m * ldc + (PERM ? perm_wb(n) : n)] = v;
            }
            if (n + 1 < N) {
                float v = hi + bias[n + 1];
                if (ACT) v = leaky(v);
                C[(size_t)m * ldc + (PERM ? perm_wb(n + 1) : n + 1)] = v;
            }
        }
    }
}

// ---------------------------------------------------------------------------
// Decoder: one block per b, 512 threads (g = tid&127, part = tid>>7 owns
// 16 of the 64 outputs). x ping-pongs through DUPLICATED u64 smem buffers
// (x[i*128+g] = (v,v)); W reads are warp-broadcast LDS.128. Inner i-loop is
// explicitly software-pipelined (load i+1 before FMAs of i).
// smem: float wb[12612] | u64 xA[8192] | u64 xB[8192]  = 181,520 B
// ---------------------------------------------------------------------------
#define DEC_SMEM_BYTES (OUTSZ_PAD * 4 + 2 * DD * NG * 8)

__global__ void __launch_bounds__(512)
k_decode(const float* __restrict__ logP, float* __restrict__ out) {
    extern __shared__ __align__(16) float wb[];
    u64* xA = (u64*)(wb + OUTSZ_PAD);
    u64* xB = xA + DD * NG;
    int b = blockIdx.x;
    int tid = threadIdx.x;

    // Vectorized load: g_wb row is already in decoder layout
    {
        const float4* s4 = (const float4*)(g_wb + (size_t)b * OUTSZ_PAD);
        float4* d4 = (float4*)wb;
        for (int i = tid; i < OUTSZ_PAD / 4; i += 512) d4[i] = s4[i];
    }
    __syncthreads();

    int g = tid & (NG - 1);
    int part = tid >> 7;
    int j0 = part * 16;

    float xin = logP[b * NG + g];
    float b0v = wb[12608];

    // First layer: xA[j] = sin(30*(xin*W0[j] + b0)), duplicated store
#pragma unroll
    for (int jj = 0; jj < 16; jj++) {
        int j = j0 + jj;
        float s = fsin(30.0f * fmaf(xin, wb[OFF_W0 + j], b0v));
        xA[j * NG + g] = pack2(s, s);
    }
    __syncthreads();

    // 3 hidden layers, software-pipelined inner loop
#pragma unroll 1
    for (int it = 0; it < 3; it++) {
        const ulonglong2* Wp = (const ulonglong2*)wb + it * 1024 + part * 4;
        const float* bs = wb + OFF_B + it * DD + j0;
        const u64* xi = (it & 1) ? xB : xA;
        u64* xo = (it & 1) ? xA : xB;

        u64 a[8];
#pragma unroll
        for (int m = 0; m < 8; m++) a[m] = pack2(bs[2 * m], bs[2 * m + 1]);

        // prologue: loads for i=0   (W row i: 16 ulonglong2; this part: 4)
        u64 xp = xi[g];
        ulonglong2 w0 = Wp[0], w1 = Wp[1], w2 = Wp[2], w3 = Wp[3];
#pragma unroll
        for (int i = 0; i < DD; i++) {
            u64 xpn;
            ulonglong2 n0, n1, n2, n3;
            if (i < DD - 1) {
                xpn = xi[(i + 1) * NG + g];
                const ulonglong2* wn = Wp + (i + 1) * 16;
                n0 = wn[0]; n1 = wn[1]; n2 = wn[2]; n3 = wn[3];
            }
            fma2(a[0], xp, w0.x); fma2(a[1], xp, w0.y);
            fma2(a[2], xp, w1.x); fma2(a[3], xp, w1.y);
            fma2(a[4], xp, w2.x); fma2(a[5], xp, w2.y);
            fma2(a[6], xp, w3.x); fma2(a[7], xp, w3.y);
            if (i < DD - 1) { xp = xpn; w0 = n0; w1 = n1; w2 = n2; w3 = n3; }
        }
#pragma unroll
        for (int m = 0; m < 8; m++) {
            float lo, hi;
            unpack2(a[m], lo, hi);
            float slo = fsin(lo), shi = fsin(hi);
            xo[(j0 + 2 * m) * NG + g] = pack2(slo, slo);
            xo[(j0 + 2 * m + 1) * NG + g] = pack2(shi, shi);
        }
        __syncthreads();
    }

    // Final dot: one thread per g (final x lives in xB after it=2)
    if (tid < NG) {
        const float* xf = (const float*)xB;
        float acc = wb[12609];
#pragma unroll
        for (int i = 0; i < DD; i++)
            acc = fmaf(xf[2 * (i * NG + tid)], wb[OFF_W4 + i], acc);
        out[b * NG + tid] = fmaf(acc, 500.0f, 1500.0f);
    }
}

// ---------------------------------------------------------------------------
extern "C" void kernel_launch(void* const* d_in, const int* in_sizes, int n_in,
                              void* d_out, int out_size) {
    (void)in_sizes; (void)n_in; (void)out_size;
    const float* z    = (const float*)d_in[0];
    const float* logP = (const float*)d_in[1];
    const float* hw0  = (const float*)d_in[2];
    const float* hb0  = (const float*)d_in[3];
    const float* hw1  = (const float*)d_in[4];
    const float* hb1  = (const float*)d_in[5];
    const float* hw2  = (const float*)d_in[6];
    const float* hb2  = (const float*)d_in[7];
    float* out = (float*)d_out;

    float *p_h0, *p_h1, *p_wb;
    cudaGetSymbolAddress((void**)&p_h0, g_h0);
    cudaGetSymbolAddress((void**)&p_h1, g_h1);
    cudaGetSymbolAddress((void**)&p_wb, g_wb);

    cudaFuncSetAttribute(k_decode, cudaFuncAttributeMaxDynamicSharedMemorySize,
                         DEC_SMEM_BYTES);

    // 1) h0 = leaky(z @ hw0 + hb0)
    k_h0<<<NB, HID>>>(z, hw0, hb0);

    // 2) h1 = leaky(h0 @ hw1 + hb1)   M=128,N=512,K=512 -> 32 blocks
    {
        dim3 grid(HID / 128, NB / 16);
        gemm_bias<16, 128, 16, 128, 1, 0><<<grid, 128>>>(p_h0, hw1, hb1, p_h1,
                                                         NB, HID, HID, HID);
    }

    // 3) wb = h1 @ hw2 + hb2 (permuted store)  M=128,N=12610,K=512 -> 396 blocks
    {
        dim3 grid((OUTSZ + 127) / 128, NB / 32);
        gemm_bias<32, 128, 16, 128, 0, 1><<<grid, 128>>>(p_h1, hw2, hb2, p_wb,
                                                         NB, OUTSZ, HID, OUTSZ_PAD);
    }

    // 4) decoder
    k_decode<<<NB, 512, DEC_SMEM_BYTES>>>(logP, out);
}

// round 8
// speedup vs baseline: 1.1889x; 1.1889x over previous
#include <cuda_runtime.h>
#include <cstdint>

#define LATENT 16
#define HID 512
#define DD 64
#define NB 128
#define NG 128
#define OUTSZ 12610
#define OUTSZ_PAD 12612

// Scratch (device globals — no allocation allowed)
__device__ float g_h0[NB * HID];
__device__ float g_h1[NB * HID];
__device__ float g_h1t_hi[HID * NB];   // transposed tf32-hi split of h1
__device__ float g_h1t_lo[HID * NB];   // transposed tf32-lo split of h1
__device__ float g_wb[NB * OUTSZ_PAD]; // PRE-PERMUTED into decoder layout

typedef unsigned long long u64;

__device__ __forceinline__ u64 pack2(float lo, float hi) {
    u64 r; asm("mov.b64 %0, {%1, %2};" : "=l"(r) : "f"(lo), "f"(hi)); return r;
}
__device__ __forceinline__ void unpack2(u64 v, float& lo, float& hi) {
    asm("mov.b64 {%0, %1}, %2;" : "=f"(lo), "=f"(hi) : "l"(v));
}
__device__ __forceinline__ void fma2(u64& d, u64 a, u64 b) {
    asm("fma.rn.f32x2 %0, %1, %2, %0;" : "+l"(d) : "l"(a), "l"(b));
}

__device__ __forceinline__ float leaky(float x) { return x > 0.0f ? x : 0.01f * x; }

// fast sin: 2-step Cody-Waite range reduction + MUFU sin (args stay < ~40)
__device__ __forceinline__ float fsin(float x) {
    float k = rintf(x * 0.15915494309189535f);
    x = fmaf(k, -6.28125f, x);
    x = fmaf(k, -1.9353071795864769e-3f, x);
    return __sinf(x);
}

// tf32 round: cvt.rna.tf32.f32 requires a .b32 destination register.
__device__ __forceinline__ float tf32r(float x) {
    uint32_t r;
    asm("cvt.rna.tf32.f32 %0, %1;" : "=r"(r) : "f"(x));
    return __uint_as_float(r);
}

// tf32 mma: D(16x8) += A(16x8) * B(8x8), fragments per PTX ISA m16n8k8
__device__ __forceinline__ void mma_tf32(float4& c, const uint32_t a[4],
                                         const uint32_t b[2]) {
    asm volatile(
        "mma.sync.aligned.m16n8k8.row.col.f32.tf32.tf32.f32 "
        "{%0,%1,%2,%3}, {%4,%5,%6,%7}, {%8,%9}, {%0,%1,%2,%3};"
        : "+f"(c.x), "+f"(c.y), "+f"(c.z), "+f"(c.w)
        : "r"(a[0]), "r"(a[1]), "r"(a[2]), "r"(a[3]), "r"(b[0]), "r"(b[1]));
}

// Decoder layout (floats): W1[0,4096) W2[4096,8192) W3[8192,12288) W0[12288,12352)
// b1[12352,12416) b2[12416,12480) b3[12480,12544) W4[12544,12608) b0[12608] b4[12609]
#define OFF_W0 12288
#define OFF_B  12352
#define OFF_W4 12544

__device__ __forceinline__ int perm_wb(int n) {
    if (n < 4161)  return (n < 64) ? 12288 + n : (n == 64 ? 12608 : n - 65);
    if (n < 8321)  return (n < 4225) ? 12352 + (n - 4161) : 4096 + (n - 4225);
    if (n < 12481) return (n < 8385) ? 12416 + (n - 8321) : 8192 + (n - 8385);
    if (n < 12545) return 12480 + (n - 12481);
    return (n < 12609) ? 12544 + (n - 12545) : 12609;
}

// ---------------------------------------------------------------------------
// Kernel 1: h0 = leaky_relu(z @ hw0 + hb0)
// ---------------------------------------------------------------------------
__global__ void k_h0(const float* __restrict__ z, const float* __restrict__ hw0,
                     const float* __restrict__ hb0) {
    int b = blockIdx.x;
    int j = threadIdx.x;
    const float* zr = z + b * LATENT;
    float acc = hb0[j];
#pragma unroll
    for (int k = 0; k < LATENT; k++) acc = fmaf(zr[k], hw0[k * HID + j], acc);
    g_h0[b * HID + j] = leaky(acc);
}

// ---------------------------------------------------------------------------
// FFMA GEMM for h1: C = leaky(A@B + bias); epilogue also emits the
// transposed tf32 hi/lo split used as the A operand of the wb MMA GEMM.
// ---------------------------------------------------------------------------
template <int BM, int BN, int BK, int NT>
__global__ void __launch_bounds__(NT)
gemm_h1(const float* __restrict__ A, const float* __restrict__ B,
        const float* __restrict__ bias, float* __restrict__ C,
        float* __restrict__ Ct_hi, float* __restrict__ Ct_lo,
        int M, int N, int K) {
    constexpr int TY = NT / 16;
    constexpr int TM = BM / TY;
    constexpr int TNH = BN / 32;
    __shared__ __align__(16) u64 As[BK][BM];
    __shared__ __align__(16) float Bs[BK][BN];

    int tid = threadIdx.x;
    int tx = tid & 15, ty = tid >> 4;
    int m0 = blockIdx.y * BM, n0 = blockIdx.x * BN;

    u64 acc[TM][TNH];
#pragma unroll
    for (int i = 0; i < TM; i++)
#pragma unroll
        for (int j = 0; j < TNH; j++) acc[i][j] = pack2(0.0f, 0.0f);

    for (int k0 = 0; k0 < K; k0 += BK) {
#pragma unroll
        for (int idx = tid; idx < BM * BK / 4; idx += NT) {
            int r = idx / (BK / 4), c4 = idx % (BK / 4);
            float4 v = *(const float4*)&A[(size_t)(m0 + r) * K + k0 + c4 * 4];
            As[c4 * 4 + 0][r] = pack2(v.x, v.x);
            As[c4 * 4 + 1][r] = pack2(v.y, v.y);
            As[c4 * 4 + 2][r] = pack2(v.z, v.z);
            As[c4 * 4 + 3][r] = pack2(v.w, v.w);
        }
#pragma unroll
        for (int idx = tid; idx < BK * BN; idx += NT) {
            int r = idx / BN, c = idx % BN;
            Bs[r][c] = B[(size_t)(k0 + r) * N + n0 + c];
        }
        __syncthreads();
#pragma unroll
        for (int k = 0; k < BK; k++) {
            u64 rap[TM], rbp[TNH];
#pragma unroll
            for (int i = 0; i < TM; i++) rap[i] = As[k][ty * TM + i];
#pragma unroll
            for (int j = 0; j < TNH; j++)
                rbp[j] = *(const u64*)&Bs[k][tx * 2 + j * 32];
#pragma unroll
            for (int i = 0; i < TM; i++)
#pragma unroll
                for (int j = 0; j < TNH; j++) fma2(acc[i][j], rap[i], rbp[j]);
        }
        __syncthreads();
    }
#pragma unroll
    for (int i = 0; i < TM; i++) {
        int m = m0 + ty * TM + i;
#pragma unroll
        for (int j = 0; j < TNH; j++) {
            float lo, hi;
            unpack2(acc[i][j], lo, hi);
            int n = n0 + tx * 2 + j * 32;
            float v0 = leaky(lo + bias[n]);
            float v1 = leaky(hi + bias[n + 1]);
            C[(size_t)m * N + n] = v0;
            C[(size_t)m * N + n + 1] = v1;
            float h0v = tf32r(v0), h1v = tf32r(v1);
            Ct_hi[(size_t)n * NB + m] = h0v;
            Ct_lo[(size_t)n * NB + m] = tf32r(v0 - h0v);
            Ct_hi[(size_t)(n + 1) * NB + m] = h1v;
            Ct_lo[(size_t)(n + 1) * NB + m] = tf32r(v1 - h1v);
        }
    }
}

// ---------------------------------------------------------------------------
// wb GEMM via mma.sync tf32, 3xTF32 split:
//   wb[128, 12610] = h1[128,512] @ hw2[512,12610] + bias  (permuted store)
// 99 CTAs x 256 threads (8 warps). CTA tile M=128 x N=128, K-step 32.
// Warp tile m64 x n32. smem tiles stride 136 floats (8-bank shift per k-row):
// fragment loads and tile stores conflict-free.
// ---------------------------------------------------------------------------
#define KT 32
#define TSTR 136
#define TILE_F (KT * TSTR)              // floats per tile
#define WB_SMEM_BYTES (4 * TILE_F * 4)  // Ah, Al, Bh, Bl

__global__ void __launch_bounds__(256)
k_wbgemm(const float* __restrict__ Ahi_g, const float* __restrict__ Alo_g,
         const float* __restrict__ Bg, const float* __restrict__ bias,
         float* __restrict__ Cout) {
    extern __shared__ __align__(16) float sm[];
    float* Ah = sm;
    float* Al = sm + TILE_F;
    float* Bh = sm + 2 * TILE_F;
    float* Bl = sm + 3 * TILE_F;

    int tid = threadIdx.x;
    int lane = tid & 31;
    int wid = tid >> 5;
    int g4 = lane >> 2;      // groupID 0..7
    int t4 = lane & 3;       // threadID in group
    int wm = wid & 1;        // m-half: 0/1  (64 rows each)
    int wn = wid >> 1;       // n-quarter: 0..3 (32 cols each)
    int n0 = blockIdx.x * 128;

    float4 acc[4][4];        // [mfrag][nfrag]
#pragma unroll
    for (int i = 0; i < 4; i++)
#pragma unroll
        for (int j = 0; j < 4; j++) acc[i][j] = make_float4(0.f, 0.f, 0.f, 0.f);

    for (int kt = 0; kt < HID; kt += KT) {
        // ---- A tiles: [32 k][128 m] from pre-split transposed h1, float4 ----
#pragma unroll
        for (int i = 0; i < 4; i++) {
            int idx = tid + i * 256;           // 0..1023 float4 slots
            int k = idx >> 5, c4 = idx & 31;
            float4 vh = *(const float4*)&Ahi_g[(size_t)(kt + k) * NB + c4 * 4];
            float4 vl = *(const float4*)&Alo_g[(size_t)(kt + k) * NB + c4 * 4];
            *(float4*)&Ah[k * TSTR + c4 * 4] = vh;
            *(float4*)&Al[k * TSTR + c4 * 4] = vl;
        }
        // ---- B tiles: [32 k][128 n] from hw2, convert hi/lo in-flight ----
        {
            int n = tid & 127;
            int kb = tid >> 7;                 // 0..1
            int gn = n0 + n;
            bool ok = gn < OUTSZ;
#pragma unroll
            for (int kk = 0; kk < KT; kk += 2) {
                float v = ok ? Bg[(size_t)(kt + kk + kb) * OUTSZ + gn] : 0.0f;
                float h = tf32r(v);
                Bh[(kk + kb) * TSTR + n] = h;
                Bl[(kk + kb) * TSTR + n] = tf32r(v - h);
            }
        }
        __syncthreads();

#pragma unroll
        for (int k8 = 0; k8 < KT; k8 += 8) {
            // A fragments: [mfrag][4 regs], hi and lo
            uint32_t ah[4][4], al[4][4];
#pragma unroll
            for (int mf = 0; mf < 4; mf++) {
                int m = wm * 64 + mf * 16 + g4;
                ah[mf][0] = __float_as_uint(Ah[(k8 + t4) * TSTR + m]);
                ah[mf][1] = __float_as_uint(Ah[(k8 + t4) * TSTR + m + 8]);
                ah[mf][2] = __float_as_uint(Ah[(k8 + t4 + 4) * TSTR + m]);
                ah[mf][3] = __float_as_uint(Ah[(k8 + t4 + 4) * TSTR + m + 8]);
                al[mf][0] = __float_as_uint(Al[(k8 + t4) * TSTR + m]);
                al[mf][1] = __float_as_uint(Al[(k8 + t4) * TSTR + m + 8]);
                al[mf][2] = __float_as_uint(Al[(k8 + t4 + 4) * TSTR + m]);
                al[mf][3] = __float_as_uint(Al[(k8 + t4 + 4) * TSTR + m + 8]);
            }
#pragma unroll
            for (int nf = 0; nf < 4; nf++) {
                int n = wn * 32 + nf * 8 + g4;
                uint32_t bh[2], bl[2];
                bh[0] = __float_as_uint(Bh[(k8 + t4) * TSTR + n]);
                bh[1] = __float_as_uint(Bh[(k8 + t4 + 4) * TSTR + n]);
                bl[0] = __float_as_uint(Bl[(k8 + t4) * TSTR + n]);
                bl[1] = __float_as_uint(Bl[(k8 + t4 + 4) * TSTR + n]);
#pragma unroll
                for (int mf = 0; mf < 4; mf++) {
                    mma_tf32(acc[mf][nf], ah[mf], bh);   // hi*hi
                    mma_tf32(acc[mf][nf], ah[mf], bl);   // hi*lo
                    mma_tf32(acc[mf][nf], al[mf], bh);   // lo*hi
                }
            }
        }
        __syncthreads();
    }

    // ---- epilogue: bias + permuted scatter to g_wb ----
#pragma unroll
    for (int mf = 0; mf < 4; mf++) {
        int m = wm * 64 + mf * 16 + g4;      // batch row
#pragma unroll
        for (int nf = 0; nf < 4; nf++) {
            int col = wn * 32 + nf * 8 + t4 * 2;
            int n = n0 + col;
            if (n < OUTSZ) {
                Cout[(size_t)m * OUTSZ_PAD + perm_wb(n)] = acc[mf][nf].x + bias[n];
                Cout[(size_t)(m + 8) * OUTSZ_PAD + perm_wb(n)] = acc[mf][nf].z + bias[n];
            }
            if (n + 1 < OUTSZ) {
                Cout[(size_t)m * OUTSZ_PAD + perm_wb(n + 1)] = acc[mf][nf].y + bias[n + 1];
                Cout[(size_t)(m + 8) * OUTSZ_PAD + perm_wb(n + 1)] = acc[mf][nf].w + bias[n + 1];
            }
        }
    }
}

// ---------------------------------------------------------------------------
// Decoder: 512 threads/block, one block per b. Pre-permuted wb row loaded
// with float4; x ping-pongs through smem x[i*128+g] (conflict-free).
// ---------------------------------------------------------------------------
#define OFF_XA 12612
#define OFF_XB 20804
#define DEC_SMEM_FLOATS (OFF_XB + DD * NG)
#define DEC_SMEM_BYTES (DEC_SMEM_FLOATS * 4)

__global__ void __launch_bounds__(512)
k_decode(const float* __restrict__ logP, float* __restrict__ out) {
    extern __shared__ __align__(16) float wb[];
    int b = blockIdx.x;
    int tid = threadIdx.x;

    {
        const float4* s4 = (const float4*)(g_wb + (size_t)b * OUTSZ_PAD);
        float4* d4 = (float4*)wb;
        for (int i = tid; i < OUTSZ_PAD / 4; i += 512) d4[i] = s4[i];
    }
    __syncthreads();

    int g = tid & (NG - 1);
    int part = tid >> 7;
    int j0 = part * 16;

    float xin = logP[b * NG + g];
    float b0v = wb[12608];
    float* xA = wb + OFF_XA;
    float* xB = wb + OFF_XB;

#pragma unroll
    for (int jj = 0; jj < 16; jj++) {
        int j = j0 + jj;
        xA[j * NG + g] = fsin(30.0f * fmaf(xin, wb[OFF_W0 + j], b0v));
    }
    __syncthreads();

#pragma unroll 1
    for (int it = 0; it < 3; it++) {
        const float* W = wb + it * DD * DD;
        const float* bs = wb + OFF_B + it * DD;
        const float* xi = (it & 1) ? xB : xA;
        float* xo = (it & 1) ? xA : xB;

        u64 a[8];
#pragma unroll
        for (int m = 0; m < 8; m++)
            a[m] = pack2(bs[j0 + 2 * m], bs[j0 + 2 * m + 1]);

#pragma unroll
        for (int i = 0; i < DD; i++) {
            float xv = xi[i * NG + g];
            u64 xp = pack2(xv, xv);
            const ulonglong2* wp = (const ulonglong2*)(W + i * DD + j0);
            ulonglong2 w0 = wp[0], w1 = wp[1], w2 = wp[2], w3 = wp[3];
            fma2(a[0], xp, w0.x); fma2(a[1], xp, w0.y);
            fma2(a[2], xp, w1.x); fma2(a[3], xp, w1.y);
            fma2(a[4], xp, w2.x); fma2(a[5], xp, w2.y);
            fma2(a[6], xp, w3.x); fma2(a[7], xp, w3.y);
        }
#pragma unroll
        for (int m = 0; m < 8; m++) {
            float lo, hi;
            unpack2(a[m], lo, hi);
            xo[(j0 + 2 * m) * NG + g] = fsin(lo);
            xo[(j0 + 2 * m + 1) * NG + g] = fsin(hi);
        }
        __syncthreads();
    }

    if (tid < NG) {
        float acc = wb[12609];
#pragma unroll
        for (int i = 0; i < DD; i++)
            acc = fmaf(xB[i * NG + tid], wb[OFF_W4 + i], acc);
        out[b * NG + tid] = fmaf(acc, 500.0f, 1500.0f);
    }
}

// ---------------------------------------------------------------------------
extern "C" void kernel_launch(void* const* d_in, const int* in_sizes, int n_in,
                              void* d_out, int out_size) {
    (void)in_sizes; (void)n_in; (void)out_size;
    const float* z    = (const float*)d_in[0];
    const float* logP = (const float*)d_in[1];
    const float* hw0  = (const float*)d_in[2];
    const float* hb0  = (const float*)d_in[3];
    const float* hw1  = (const float*)d_in[4];
    const float* hb1  = (const float*)d_in[5];
    const float* hw2  = (const float*)d_in[6];
    const float* hb2  = (const float*)d_in[7];
    float* out = (float*)d_out;

    float *p_h0, *p_h1, *p_h1t_hi, *p_h1t_lo, *p_wb;
    cudaGetSymbolAddress((void**)&p_h0, g_h0);
    cudaGetSymbolAddress((void**)&p_h1, g_h1);
    cudaGetSymbolAddress((void**)&p_h1t_hi, g_h1t_hi);
    cudaGetSymbolAddress((void**)&p_h1t_lo, g_h1t_lo);
    cudaGetSymbolAddress((void**)&p_wb, g_wb);

    cudaFuncSetAttribute(k_decode, cudaFuncAttributeMaxDynamicSharedMemorySize,
                         DEC_SMEM_BYTES);
    cudaFuncSetAttribute(k_wbgemm, cudaFuncAttributeMaxDynamicSharedMemorySize,
                         WB_SMEM_BYTES);

    // 1) h0
    k_h0<<<NB, HID>>>(z, hw0, hb0);

    // 2) h1 = leaky(h0 @ hw1 + hb1) + transposed tf32 split for wb GEMM
    {
        dim3 grid(HID / 64, NB / 16);
        gemm_h1<16, 64, 16, 128><<<grid, 128>>>(p_h0, hw1, hb1, p_h1,
                                                p_h1t_hi, p_h1t_lo,
                                                NB, HID, HID);
    }

    // 3) wb = h1 @ hw2 + hb2 via mma.sync 3xTF32, permuted store
    k_wbgemm<<<(OUTSZ + 127) / 128, 256, WB_SMEM_BYTES>>>(p_h1t_hi, p_h1t_lo,
                                                          hw2, hb2, p_wb);

    // 4) decoder
    k_decode<<<NB, 512, DEC_SMEM_BYTES>>>(logP, out);
}

// round 9
// speedup vs baseline: 1.3034x; 1.0963x over previous
#include <cuda_runtime.h>
#include <cstdint>

#define LATENT 16
#define HID 512
#define DD 64
#define NB 128
#define NG 128
#define OUTSZ 12610
#define OUTSZ_PAD 12612

// Scratch (device globals — no allocation allowed)
__device__ float g_h0[NB * HID];
__device__ float g_h1[NB * HID];
__device__ float g_h1t_hi[HID * NB];   // transposed tf32-hi split of h1
__device__ float g_h1t_lo[HID * NB];   // transposed tf32-lo split of h1
__device__ float g_wb[NB * OUTSZ_PAD]; // PRE-PERMUTED into decoder layout

typedef unsigned long long u64;

__device__ __forceinline__ u64 pack2(float lo, float hi) {
    u64 r; asm("mov.b64 %0, {%1, %2};" : "=l"(r) : "f"(lo), "f"(hi)); return r;
}
__device__ __forceinline__ void unpack2(u64 v, float& lo, float& hi) {
    asm("mov.b64 {%0, %1}, %2;" : "=f"(lo), "=f"(hi) : "l"(v));
}
__device__ __forceinline__ void fma2(u64& d, u64 a, u64 b) {
    asm("fma.rn.f32x2 %0, %1, %2, %0;" : "+l"(d) : "l"(a), "l"(b));
}

__device__ __forceinline__ float leaky(float x) { return x > 0.0f ? x : 0.01f * x; }

// fast sin: 2-step Cody-Waite range reduction + MUFU sin (args stay < ~40)
__device__ __forceinline__ float fsin(float x) {
    float k = rintf(x * 0.15915494309189535f);
    x = fmaf(k, -6.28125f, x);
    x = fmaf(k, -1.9353071795864769e-3f, x);
    return __sinf(x);
}

// tf32 round (cvt.rna.tf32.f32 needs a .b32 destination)
__device__ __forceinline__ float tf32r(float x) {
    uint32_t r;
    asm("cvt.rna.tf32.f32 %0, %1;" : "=r"(r) : "f"(x));
    return __uint_as_float(r);
}

// tf32 mma m16n8k8
__device__ __forceinline__ void mma_tf32(float4& c, const uint32_t a[4],
                                         const uint32_t b[2]) {
    asm volatile(
        "mma.sync.aligned.m16n8k8.row.col.f32.tf32.tf32.f32 "
        "{%0,%1,%2,%3}, {%4,%5,%6,%7}, {%8,%9}, {%0,%1,%2,%3};"
        : "+f"(c.x), "+f"(c.y), "+f"(c.z), "+f"(c.w)
        : "r"(a[0]), "r"(a[1]), "r"(a[2]), "r"(a[3]), "r"(b[0]), "r"(b[1]));
}

// Decoder layout (floats): W1[0,4096) W2[4096,8192) W3[8192,12288) W0[12288,12352)
// b1[12352,12416) b2[12416,12480) b3[12480,12544) W4[12544,12608) b0[12608] b4[12609]
#define OFF_W0 12288
#define OFF_B  12352
#define OFF_W4 12544

__device__ __forceinline__ int perm_wb(int n) {
    if (n < 4161)  return (n < 64) ? 12288 + n : (n == 64 ? 12608 : n - 65);
    if (n < 8321)  return (n < 4225) ? 12352 + (n - 4161) : 4096 + (n - 4225);
    if (n < 12481) return (n < 8385) ? 12416 + (n - 8321) : 8192 + (n - 8385);
    if (n < 12545) return 12480 + (n - 12481);
    return (n < 12609) ? 12544 + (n - 12545) : 12609;
}

// ---------------------------------------------------------------------------
// Kernel 1: h0 = leaky_relu(z @ hw0 + hb0)
// ---------------------------------------------------------------------------
__global__ void k_h0(const float* __restrict__ z, const float* __restrict__ hw0,
                     const float* __restrict__ hb0) {
    int b = blockIdx.x;
    int j = threadIdx.x;
    const float* zr = z + b * LATENT;
    float acc = hb0[j];
#pragma unroll
    for (int k = 0; k < LATENT; k++) acc = fmaf(zr[k], hw0[k * HID + j], acc);
    g_h0[b * HID + j] = leaky(acc);
}

// ---------------------------------------------------------------------------
// FFMA GEMM for h1, register-staged prefetch pipeline.
// BM=16, BN=64, BK=16, 128 threads -> 64 blocks. Epilogue also emits the
// transposed tf32 hi/lo split (A operand of the wb MMA GEMM).
// ---------------------------------------------------------------------------
#define H1_BM 16
#define H1_BN 64
#define H1_BK 16

__global__ void __launch_bounds__(128)
gemm_h1(const float* __restrict__ A, const float* __restrict__ B,
        const float* __restrict__ bias, float* __restrict__ C,
        float* __restrict__ Ct_hi, float* __restrict__ Ct_lo) {
    constexpr int N = HID, K = HID;
    __shared__ __align__(16) u64 As[H1_BK][H1_BM];
    __shared__ __align__(16) float Bs[H1_BK][H1_BN];

    int tid = threadIdx.x;
    int tx = tid & 15, ty = tid >> 4;     // ty 0..7 -> TM = 2
    int m0 = blockIdx.y * H1_BM, n0 = blockIdx.x * H1_BN;

    u64 acc[2][2];
#pragma unroll
    for (int i = 0; i < 2; i++)
#pragma unroll
        for (int j = 0; j < 2; j++) acc[i][j] = pack2(0.0f, 0.0f);

    // prefetch registers
    float4 pa;                 // valid for tid < 64
    float pb[8];
    int par = tid >> 2, pac4 = tid & 3;   // A: 64 float4 slots (16 rows x 4)
    int pbn = tid & 63, pbk0 = tid >> 6;  // B: rows pbk0, pbk0+2, ... (8 rows)

    auto ldg_tile = [&](int k0, float4& a4, float pbv[8]) {
        if (tid < 64)
            a4 = *(const float4*)&A[(size_t)(m0 + par) * K + k0 + pac4 * 4];
#pragma unroll
        for (int r = 0; r < 8; r++)
            pbv[r] = B[(size_t)(k0 + pbk0 + r * 2) * N + n0 + pbn];
    };
    auto sts_tile = [&](const float4& a4, const float pbv[8]) {
        if (tid < 64) {
            As[pac4 * 4 + 0][par] = pack2(a4.x, a4.x);
            As[pac4 * 4 + 1][par] = pack2(a4.y, a4.y);
            As[pac4 * 4 + 2][par] = pack2(a4.z, a4.z);
            As[pac4 * 4 + 3][par] = pack2(a4.w, a4.w);
        }
#pragma unroll
        for (int r = 0; r < 8; r++) Bs[pbk0 + r * 2][pbn] = pbv[r];
    };

    ldg_tile(0, pa, pb);
    sts_tile(pa, pb);
    __syncthreads();

    for (int t = 0; t < K / H1_BK; t++) {
        if (t + 1 < K / H1_BK) ldg_tile((t + 1) * H1_BK, pa, pb);
#pragma unroll
        for (int k = 0; k < H1_BK; k++) {
            u64 ra0 = As[k][ty * 2], ra1 = As[k][ty * 2 + 1];
            u64 rb0 = *(const u64*)&Bs[k][tx * 2];
            u64 rb1 = *(const u64*)&Bs[k][tx * 2 + 32];
            fma2(acc[0][0], ra0, rb0); fma2(acc[0][1], ra0, rb1);
            fma2(acc[1][0], ra1, rb0); fma2(acc[1][1], ra1, rb1);
        }
        __syncthreads();
        if (t + 1 < K / H1_BK) {
            sts_tile(pa, pb);
            __syncthreads();
        }
    }

#pragma unroll
    for (int i = 0; i < 2; i++) {
        int m = m0 + ty * 2 + i;
#pragma unroll
        for (int j = 0; j < 2; j++) {
            float lo, hi;
            unpack2(acc[i][j], lo, hi);
            int n = n0 + tx * 2 + j * 32;
            float v0 = leaky(lo + bias[n]);
            float v1 = leaky(hi + bias[n + 1]);
            C[(size_t)m * N + n] = v0;
            C[(size_t)m * N + n + 1] = v1;
            float h0v = tf32r(v0), h1v = tf32r(v1);
            Ct_hi[(size_t)n * NB + m] = h0v;
            Ct_lo[(size_t)n * NB + m] = tf32r(v0 - h0v);
            Ct_hi[(size_t)(n + 1) * NB + m] = h1v;
            Ct_lo[(size_t)(n + 1) * NB + m] = tf32r(v1 - h1v);
        }
    }
}

// ---------------------------------------------------------------------------
// wb GEMM via mma.sync tf32 (3xTF32), register-staged prefetch pipeline.
// 99 CTAs x 256 threads, CTA tile M=128 x N=128, K-step 32, warp m64 x n32.
// smem stride 136 floats: conflict-free fragment loads/stores.
// ---------------------------------------------------------------------------
#define KT 32
#define TSTR 136
#define TILE_F (KT * TSTR)
#define WB_SMEM_BYTES (4 * TILE_F * 4)

__global__ void __launch_bounds__(256)
k_wbgemm(const float* __restrict__ Ahi_g, const float* __restrict__ Alo_g,
         const float* __restrict__ Bg, const float* __restrict__ bias,
         float* __restrict__ Cout) {
    extern __shared__ __align__(16) float sm[];
    float* Ah = sm;
    float* Al = sm + TILE_F;
    float* Bh = sm + 2 * TILE_F;
    float* Bl = sm + 3 * TILE_F;

    int tid = threadIdx.x;
    int lane = tid & 31;
    int wid = tid >> 5;
    int g4 = lane >> 2;
    int t4 = lane & 3;
    int wm = wid & 1;
    int wn = wid >> 1;
    int n0 = blockIdx.x * 128;

    int pbn = tid & 127, pbkb = tid >> 7;
    bool pbok = (n0 + pbn) < OUTSZ;

    float4 acc[4][4];
#pragma unroll
    for (int i = 0; i < 4; i++)
#pragma unroll
        for (int j = 0; j < 4; j++) acc[i][j] = make_float4(0.f, 0.f, 0.f, 0.f);

    float4 pah[4], pal[4];
    float pb[16];

    auto ldg_tile = [&](int kt) {
#pragma unroll
        for (int i = 0; i < 4; i++) {
            int idx = tid + i * 256;
            int k = idx >> 5, c4 = idx & 31;
            pah[i] = *(const float4*)&Ahi_g[(size_t)(kt + k) * NB + c4 * 4];
            pal[i] = *(const float4*)&Alo_g[(size_t)(kt + k) * NB + c4 * 4];
        }
        const float* bp = Bg + (size_t)(kt + pbkb) * OUTSZ + n0 + pbn;
#pragma unroll
        for (int r = 0; r < 16; r++)
            pb[r] = pbok ? bp[(size_t)(r * 2) * OUTSZ] : 0.0f;
    };
    auto sts_tile = [&]() {
#pragma unroll
        for (int i = 0; i < 4; i++) {
            int idx = tid + i * 256;
            int k = idx >> 5, c4 = idx & 31;
            *(float4*)&Ah[k * TSTR + c4 * 4] = pah[i];
            *(float4*)&Al[k * TSTR + c4 * 4] = pal[i];
        }
#pragma unroll
        for (int r = 0; r < 16; r++) {
            float h = tf32r(pb[r]);
            Bh[(r * 2 + pbkb) * TSTR + pbn] = h;
            Bl[(r * 2 + pbkb) * TSTR + pbn] = tf32r(pb[r] - h);
        }
    };

    ldg_tile(0);
    sts_tile();
    __syncthreads();

    for (int t = 0; t < HID / KT; t++) {
        if (t + 1 < HID / KT) ldg_tile((t + 1) * KT);

#pragma unroll
        for (int k8 = 0; k8 < KT; k8 += 8) {
            uint32_t ah[4][4], al[4][4];
#pragma unroll
            for (int mf = 0; mf < 4; mf++) {
                int m = wm * 64 + mf * 16 + g4;
                ah[mf][0] = __float_as_uint(Ah[(k8 + t4) * TSTR + m]);
                ah[mf][1] = __float_as_uint(Ah[(k8 + t4) * TSTR + m + 8]);
                ah[mf][2] = __float_as_uint(Ah[(k8 + t4 + 4) * TSTR + m]);
                ah[mf][3] = __float_as_uint(Ah[(k8 + t4 + 4) * TSTR + m + 8]);
                al[mf][0] = __float_as_uint(Al[(k8 + t4) * TSTR + m]);
                al[mf][1] = __float_as_uint(Al[(k8 + t4) * TSTR + m + 8]);
                al[mf][2] = __float_as_uint(Al[(k8 + t4 + 4) * TSTR + m]);
                al[mf][3] = __float_as_uint(Al[(k8 + t4 + 4) * TSTR + m + 8]);
            }
#pragma unroll
            for (int nf = 0; nf < 4; nf++) {
                int n = wn * 32 + nf * 8 + g4;
                uint32_t bh[2], bl[2];
                bh[0] = __float_as_uint(Bh[(k8 + t4) * TSTR + n]);
                bh[1] = __float_as_uint(Bh[(k8 + t4 + 4) * TSTR + n]);
                bl[0] = __float_as_uint(Bl[(k8 + t4) * TSTR + n]);
                bl[1] = __float_as_uint(Bl[(k8 + t4 + 4) * TSTR + n]);
#pragma unroll
                for (int mf = 0; mf < 4; mf++) {
                    mma_tf32(acc[mf][nf], ah[mf], bh);
                    mma_tf32(acc[mf][nf], ah[mf], bl);
                    mma_tf32(acc[mf][nf], al[mf], bh);
                }
            }
        }
        __syncthreads();
        if (t + 1 < HID / KT) {
            sts_tile();
            __syncthreads();
        }
    }

    // epilogue: bias + permuted scatter
#pragma unroll
    for (int mf = 0; mf < 4; mf++) {
        int m = wm * 64 + mf * 16 + g4;
#pragma unroll
        for (int nf = 0; nf < 4; nf++) {
            int n = n0 + wn * 32 + nf * 8 + t4 * 2;
            if (n < OUTSZ) {
                Cout[(size_t)m * OUTSZ_PAD + perm_wb(n)] = acc[mf][nf].x + bias[n];
                Cout[(size_t)(m + 8) * OUTSZ_PAD + perm_wb(n)] = acc[mf][nf].z + bias[n];
            }
            if (n + 1 < OUTSZ) {
                Cout[(size_t)m * OUTSZ_PAD + perm_wb(n + 1)] = acc[mf][nf].y + bias[n + 1];
                Cout[(size_t)(m + 8) * OUTSZ_PAD + perm_wb(n + 1)] = acc[mf][nf].w + bias[n + 1];
            }
        }
    }
}

// ---------------------------------------------------------------------------
// Decoder: 1024 threads/block (8 parts x 128 g), one block per b.
// Each thread computes 8 of 64 layer outputs; x ping-pongs through smem
// x[i*128+g] (warp lanes = consecutive g -> conflict-free; W reads broadcast).
// ---------------------------------------------------------------------------
#define OFF_XA 12612
#define OFF_XB 20804
#define DEC_SMEM_FLOATS (OFF_XB + DD * NG)
#define DEC_SMEM_BYTES (DEC_SMEM_FLOATS * 4)

__global__ void __launch_bounds__(1024)
k_decode(const float* __restrict__ logP, float* __restrict__ out) {
    extern __shared__ __align__(16) float wb[];
    int b = blockIdx.x;
    int tid = threadIdx.x;

    {
        const float4* s4 = (const float4*)(g_wb + (size_t)b * OUTSZ_PAD);
        float4* d4 = (float4*)wb;
        for (int i = tid; i < OUTSZ_PAD / 4; i += 1024) d4[i] = s4[i];
    }
    __syncthreads();

    int g = tid & (NG - 1);
    int part = tid >> 7;        // 0..7
    int j0 = part * 8;

    float xin = logP[b * NG + g];
    float b0v = wb[12608];
    float* xA = wb + OFF_XA;
    float* xB = wb + OFF_XB;

#pragma unroll
    for (int jj = 0; jj < 8; jj++) {
        int j = j0 + jj;
        xA[j * NG + g] = fsin(30.0f * fmaf(xin, wb[OFF_W0 + j], b0v));
    }
    __syncthreads();

#pragma unroll 1
    for (int it = 0; it < 3; it++) {
        const float* W = wb + it * DD * DD;
        const float* bs = wb + OFF_B + it * DD;
        const float* xi = (it & 1) ? xB : xA;
        float* xo = (it & 1) ? xA : xB;

        u64 a[4];
#pragma unroll
        for (int m = 0; m < 4; m++)
            a[m] = pack2(bs[j0 + 2 * m], bs[j0 + 2 * m + 1]);

#pragma unroll
        for (int i = 0; i < DD; i++) {
            float xv = xi[i * NG + g];
            u64 xp = pack2(xv, xv);
            const ulonglong2* wp = (const ulonglong2*)(W + i * DD + j0);
            ulonglong2 w0 = wp[0], w1 = wp[1];
            fma2(a[0], xp, w0.x); fma2(a[1], xp, w0.y);
            fma2(a[2], xp, w1.x); fma2(a[3], xp, w1.y);
        }
#pragma unroll
        for (int m = 0; m < 4; m++) {
            float lo, hi;
            unpack2(a[m], lo, hi);
            xo[(j0 + 2 * m) * NG + g] = fsin(lo);
            xo[(j0 + 2 * m + 1) * NG + g] = fsin(hi);
        }
        __syncthreads();
    }

    if (tid < NG) {
        float acc = wb[12609];
#pragma unroll
        for (int i = 0; i < DD; i++)
            acc = fmaf(xB[i * NG + tid], wb[OFF_W4 + i], acc);
        out[b * NG + tid] = fmaf(acc, 500.0f, 1500.0f);
    }
}

// ---------------------------------------------------------------------------
extern "C" void kernel_launch(void* const* d_in, const int* in_sizes, int n_in,
                              void* d_out, int out_size) {
    (void)in_sizes; (void)n_in; (void)out_size;
    const float* z    = (const float*)d_in[0];
    const float* logP = (const float*)d_in[1];
    const float* hw0  = (const float*)d_in[2];
    const float* hb0  = (const float*)d_in[3];
    const float* hw1  = (const float*)d_in[4];
    const float* hb1  = (const float*)d_in[5];
    const float* hw2  = (const float*)d_in[6];
    const float* hb2  = (const float*)d_in[7];
    float* out = (float*)d_out;

    float *p_h0, *p_h1, *p_h1t_hi, *p_h1t_lo, *p_wb;
    cudaGetSymbolAddress((void**)&p_h0, g_h0);
    cudaGetSymbolAddress((void**)&p_h1, g_h1);
    cudaGetSymbolAddress((void**)&p_h1t_hi, g_h1t_hi);
    cudaGetSymbolAddress((void**)&p_h1t_lo, g_h1t_lo);
    cudaGetSymbolAddress((void**)&p_wb, g_wb);

    cudaFuncSetAttribute(k_decode, cudaFuncAttributeMaxDynamicSharedMemorySize,
                         DEC_SMEM_BYTES);
    cudaFuncSetAttribute(k_wbgemm, cudaFuncAttributeMaxDynamicSharedMemorySize,
                         WB_SMEM_BYTES);

    // 1) h0
    k_h0<<<NB, HID>>>(z, hw0, hb0);

    // 2) h1 = leaky(h0 @ hw1 + hb1) + transposed tf32 split
    {
        dim3 grid(HID / H1_BN, NB / H1_BM);   // 8 x 8 = 64 blocks
        gemm_h1<<<grid, 128>>>(p_h0, hw1, hb1, p_h1, p_h1t_hi, p_h1t_lo);
    }

    // 3) wb = h1 @ hw2 + hb2 via mma.sync 3xTF32, permuted store
    k_wbgemm<<<(OUTSZ + 127) / 128, 256, WB_SMEM_BYTES>>>(p_h1t_hi, p_h1t_lo,
                                                          hw2, hb2, p_wb);

    // 4) decoder
    k_decode<<<NB, 1024, DEC_SMEM_BYTES>>>(logP, out);
}

// round 10
// speedup vs baseline: 1.4605x; 1.1206x over previous
#include <cuda_runtime.h>
#include <cstdint>

#define LATENT 16
#define HID 512
#define DD 64
#define NB 128
#define NG 128
#define OUTSZ 12610
#define OUTSZ_PAD 12612

// Scratch (device globals — no allocation allowed)
__device__ float g_h0[NB * HID];
__device__ float g_h1[NB * HID];
__device__ float g_h1t_hi[HID * NB];   // transposed tf32-hi split of h1
__device__ float g_h1t_lo[HID * NB];   // transposed tf32-lo split of h1
__device__ float g_wb[NB * OUTSZ_PAD]; // PRE-PERMUTED into decoder layout

typedef unsigned long long u64;

__device__ __forceinline__ u64 pack2(float lo, float hi) {
    u64 r; asm("mov.b64 %0, {%1, %2};" : "=l"(r) : "f"(lo), "f"(hi)); return r;
}
__device__ __forceinline__ void unpack2(u64 v, float& lo, float& hi) {
    asm("mov.b64 {%0, %1}, %2;" : "=f"(lo), "=f"(hi) : "l"(v));
}
__device__ __forceinline__ void fma2(u64& d, u64 a, u64 b) {
    asm("fma.rn.f32x2 %0, %1, %2, %0;" : "+l"(d) : "l"(a), "l"(b));
}

__device__ __forceinline__ float leaky(float x) { return x > 0.0f ? x : 0.01f * x; }

// fast sin: 2-step Cody-Waite range reduction + MUFU sin (args stay < ~40)
__device__ __forceinline__ float fsin(float x) {
    float k = rintf(x * 0.15915494309189535f);
    x = fmaf(k, -6.28125f, x);
    x = fmaf(k, -1.9353071795864769e-3f, x);
    return __sinf(x);
}

// tf32 round (cvt.rna.tf32.f32 needs a .b32 destination)
__device__ __forceinline__ float tf32r(float x) {
    uint32_t r;
    asm("cvt.rna.tf32.f32 %0, %1;" : "=r"(r) : "f"(x));
    return __uint_as_float(r);
}

// tf32 mma m16n8k8 (fragment mappings validated in rounds 8-9)
__device__ __forceinline__ void mma_tf32(float4& c, const uint32_t a[4],
                                         const uint32_t b[2]) {
    asm volatile(
        "mma.sync.aligned.m16n8k8.row.col.f32.tf32.tf32.f32 "
        "{%0,%1,%2,%3}, {%4,%5,%6,%7}, {%8,%9}, {%0,%1,%2,%3};"
        : "+f"(c.x), "+f"(c.y), "+f"(c.z), "+f"(c.w)
        : "r"(a[0]), "r"(a[1]), "r"(a[2]), "r"(a[3]), "r"(b[0]), "r"(b[1]));
}

// Decoder layout (floats): W1[0,4096) W2[4096,8192) W3[8192,12288) W0[12288,12352)
// b1[12352,12416) b2[12416,12480) b3[12480,12544) W4[12544,12608) b0[12608] b4[12609]
#define OFF_W0 12288
#define OFF_B  12352
#define OFF_W4 12544

__device__ __forceinline__ int perm_wb(int n) {
    if (n < 4161)  return (n < 64) ? 12288 + n : (n == 64 ? 12608 : n - 65);
    if (n < 8321)  return (n < 4225) ? 12352 + (n - 4161) : 4096 + (n - 4225);
    if (n < 12481) return (n < 8385) ? 12416 + (n - 8321) : 8192 + (n - 8385);
    if (n < 12545) return 12480 + (n - 12481);
    return (n < 12609) ? 12544 + (n - 12545) : 12609;
}

// ---------------------------------------------------------------------------
// Kernel 1: h0 = leaky_relu(z @ hw0 + hb0)
// ---------------------------------------------------------------------------
__global__ void k_h0(const float* __restrict__ z, const float* __restrict__ hw0,
                     const float* __restrict__ hb0) {
    int b = blockIdx.x;
    int j = threadIdx.x;
    const float* zr = z + b * LATENT;
    float acc = hb0[j];
#pragma unroll
    for (int k = 0; k < LATENT; k++) acc = fmaf(zr[k], hw0[k * HID + j], acc);
    g_h0[b * HID + j] = leaky(acc);
}

// ---------------------------------------------------------------------------
// FFMA GEMM for h1, register-staged prefetch pipeline. Epilogue emits the
// transposed tf32 hi/lo split (A operand of the wb MMA GEMM).
// ---------------------------------------------------------------------------
#define H1_BM 16
#define H1_BN 64
#define H1_BK 16

__global__ void __launch_bounds__(128)
gemm_h1(const float* __restrict__ A, const float* __restrict__ B,
        const float* __restrict__ bias, float* __restrict__ C,
        float* __restrict__ Ct_hi, float* __restrict__ Ct_lo) {
    constexpr int N = HID, K = HID;
    __shared__ __align__(16) u64 As[H1_BK][H1_BM];
    __shared__ __align__(16) float Bs[H1_BK][H1_BN];

    int tid = threadIdx.x;
    int tx = tid & 15, ty = tid >> 4;
    int m0 = blockIdx.y * H1_BM, n0 = blockIdx.x * H1_BN;

    u64 acc[2][2];
#pragma unroll
    for (int i = 0; i < 2; i++)
#pragma unroll
        for (int j = 0; j < 2; j++) acc[i][j] = pack2(0.0f, 0.0f);

    float4 pa;
    float pb[8];
    int par = tid >> 2, pac4 = tid & 3;
    int pbn = tid & 63, pbk0 = tid >> 6;

    auto ldg_tile = [&](int k0, float4& a4, float pbv[8]) {
        if (tid < 64)
            a4 = *(const float4*)&A[(size_t)(m0 + par) * K + k0 + pac4 * 4];
#pragma unroll
        for (int r = 0; r < 8; r++)
            pbv[r] = B[(size_t)(k0 + pbk0 + r * 2) * N + n0 + pbn];
    };
    auto sts_tile = [&](const float4& a4, const float pbv[8]) {
        if (tid < 64) {
            As[pac4 * 4 + 0][par] = pack2(a4.x, a4.x);
            As[pac4 * 4 + 1][par] = pack2(a4.y, a4.y);
            As[pac4 * 4 + 2][par] = pack2(a4.z, a4.z);
            As[pac4 * 4 + 3][par] = pack2(a4.w, a4.w);
        }
#pragma unroll
        for (int r = 0; r < 8; r++) Bs[pbk0 + r * 2][pbn] = pbv[r];
    };

    ldg_tile(0, pa, pb);
    sts_tile(pa, pb);
    __syncthreads();

    for (int t = 0; t < K / H1_BK; t++) {
        if (t + 1 < K / H1_BK) ldg_tile((t + 1) * H1_BK, pa, pb);
#pragma unroll
        for (int k = 0; k < H1_BK; k++) {
            u64 ra0 = As[k][ty * 2], ra1 = As[k][ty * 2 + 1];
            u64 rb0 = *(const u64*)&Bs[k][tx * 2];
            u64 rb1 = *(const u64*)&Bs[k][tx * 2 + 32];
            fma2(acc[0][0], ra0, rb0); fma2(acc[0][1], ra0, rb1);
            fma2(acc[1][0], ra1, rb0); fma2(acc[1][1], ra1, rb1);
        }
        __syncthreads();
        if (t + 1 < K / H1_BK) {
            sts_tile(pa, pb);
            __syncthreads();
        }
    }

#pragma unroll
    for (int i = 0; i < 2; i++) {
        int m = m0 + ty * 2 + i;
#pragma unroll
        for (int j = 0; j < 2; j++) {
            float lo, hi;
            unpack2(acc[i][j], lo, hi);
            int n = n0 + tx * 2 + j * 32;
            float v0 = leaky(lo + bias[n]);
            float v1 = leaky(hi + bias[n + 1]);
            C[(size_t)m * N + n] = v0;
            C[(size_t)m * N + n + 1] = v1;
            float h0v = tf32r(v0), h1v = tf32r(v1);
            Ct_hi[(size_t)n * NB + m] = h0v;
            Ct_lo[(size_t)n * NB + m] = tf32r(v0 - h0v);
            Ct_hi[(size_t)(n + 1) * NB + m] = h1v;
            Ct_lo[(size_t)(n + 1) * NB + m] = tf32r(v1 - h1v);
        }
    }
}

// ---------------------------------------------------------------------------
// wb GEMM via mma.sync tf32 (3xTF32), prefetch pipeline, N-tile 96 -> 132 CTAs
// (one full wave on 148 SMs). CTA tile M=128 x N=96; warp m64 x n24.
// ---------------------------------------------------------------------------
#define KT 32
#define BNW 96
#define TSTR 136
#define TILE_AF (KT * TSTR)
#define TILE_BF (KT * TSTR)
#define WB_SMEM_BYTES ((2 * TILE_AF + 2 * TILE_BF) * 4)

__global__ void __launch_bounds__(256)
k_wbgemm(const float* __restrict__ Ahi_g, const float* __restrict__ Alo_g,
         const float* __restrict__ Bg, const float* __restrict__ bias,
         float* __restrict__ Cout) {
    extern __shared__ __align__(16) float sm[];
    float* Ah = sm;
    float* Al = sm + TILE_AF;
    float* Bh = sm + 2 * TILE_AF;
    float* Bl = sm + 2 * TILE_AF + TILE_BF;

    int tid = threadIdx.x;
    int lane = tid & 31;
    int wid = tid >> 5;
    int g4 = lane >> 2;
    int t4 = lane & 3;
    int wm = wid & 1;        // m-half (64 rows)
    int wn = wid >> 1;       // n-quarter (24 cols)
    int n0 = blockIdx.x * BNW;

    float4 acc[4][3];
#pragma unroll
    for (int i = 0; i < 4; i++)
#pragma unroll
        for (int j = 0; j < 3; j++) acc[i][j] = make_float4(0.f, 0.f, 0.f, 0.f);

    float4 pah[4], pal[4];
    float pb[12];

    auto ldg_tile = [&](int kt) {
#pragma unroll
        for (int i = 0; i < 4; i++) {
            int idx = tid + i * 256;
            int k = idx >> 5, c4 = idx & 31;
            pah[i] = *(const float4*)&Ahi_g[(size_t)(kt + k) * NB + c4 * 4];
            pal[i] = *(const float4*)&Alo_g[(size_t)(kt + k) * NB + c4 * 4];
        }
#pragma unroll
        for (int r = 0; r < 12; r++) {
            int idx = tid + r * 256;            // 0..3071
            int n = idx % BNW, k = idx / BNW;
            int gn = n0 + n;
            pb[r] = (gn < OUTSZ) ? Bg[(size_t)(kt + k) * OUTSZ + gn] : 0.0f;
        }
    };
    auto sts_tile = [&]() {
#pragma unroll
        for (int i = 0; i < 4; i++) {
            int idx = tid + i * 256;
            int k = idx >> 5, c4 = idx & 31;
            *(float4*)&Ah[k * TSTR + c4 * 4] = pah[i];
            *(float4*)&Al[k * TSTR + c4 * 4] = pal[i];
        }
#pragma unroll
        for (int r = 0; r < 12; r++) {
            int idx = tid + r * 256;
            int n = idx % BNW, k = idx / BNW;
            float h = tf32r(pb[r]);
            Bh[k * TSTR + n] = h;
            Bl[k * TSTR + n] = tf32r(pb[r] - h);
        }
    };

    ldg_tile(0);
    sts_tile();
    __syncthreads();

    for (int t = 0; t < HID / KT; t++) {
        if (t + 1 < HID / KT) ldg_tile((t + 1) * KT);

#pragma unroll
        for (int k8 = 0; k8 < KT; k8 += 8) {
            uint32_t ah[4][4], al[4][4];
#pragma unroll
            for (int mf = 0; mf < 4; mf++) {
                int m = wm * 64 + mf * 16 + g4;
                ah[mf][0] = __float_as_uint(Ah[(k8 + t4) * TSTR + m]);
                ah[mf][1] = __float_as_uint(Ah[(k8 + t4) * TSTR + m + 8]);
                ah[mf][2] = __float_as_uint(Ah[(k8 + t4 + 4) * TSTR + m]);
                ah[mf][3] = __float_as_uint(Ah[(k8 + t4 + 4) * TSTR + m + 8]);
                al[mf][0] = __float_as_uint(Al[(k8 + t4) * TSTR + m]);
                al[mf][1] = __float_as_uint(Al[(k8 + t4) * TSTR + m + 8]);
                al[mf][2] = __float_as_uint(Al[(k8 + t4 + 4) * TSTR + m]);
                al[mf][3] = __float_as_uint(Al[(k8 + t4 + 4) * TSTR + m + 8]);
            }
#pragma unroll
            for (int nf = 0; nf < 3; nf++) {
                int n = wn * 24 + nf * 8 + g4;
                uint32_t bh[2], bl[2];
                bh[0] = __float_as_uint(Bh[(k8 + t4) * TSTR + n]);
                bh[1] = __float_as_uint(Bh[(k8 + t4 + 4) * TSTR + n]);
                bl[0] = __float_as_uint(Bl[(k8 + t4) * TSTR + n]);
                bl[1] = __float_as_uint(Bl[(k8 + t4 + 4) * TSTR + n]);
#pragma unroll
                for (int mf = 0; mf < 4; mf++) {
                    mma_tf32(acc[mf][nf], ah[mf], bh);
                    mma_tf32(acc[mf][nf], ah[mf], bl);
                    mma_tf32(acc[mf][nf], al[mf], bh);
                }
            }
        }
        __syncthreads();
        if (t + 1 < HID / KT) {
            sts_tile();
            __syncthreads();
        }
    }

    // epilogue: bias + permuted scatter
#pragma unroll
    for (int mf = 0; mf < 4; mf++) {
        int m = wm * 64 + mf * 16 + g4;
#pragma unroll
        for (int nf = 0; nf < 3; nf++) {
            int n = n0 + wn * 24 + nf * 8 + t4 * 2;
            if (n < OUTSZ) {
                Cout[(size_t)m * OUTSZ_PAD + perm_wb(n)] = acc[mf][nf].x + bias[n];
                Cout[(size_t)(m + 8) * OUTSZ_PAD + perm_wb(n)] = acc[mf][nf].z + bias[n];
            }
            if (n + 1 < OUTSZ) {
                Cout[(size_t)m * OUTSZ_PAD + perm_wb(n + 1)] = acc[mf][nf].y + bias[n + 1];
                Cout[(size_t)(m + 8) * OUTSZ_PAD + perm_wb(n + 1)] = acc[mf][nf].w + bias[n + 1];
            }
        }
    }
}

// ---------------------------------------------------------------------------
// Decoder via mma.sync tf32 (2-split): per block b, the 3 hidden layers are
// X[128g x 64] @ W[64 x 64] GEMMs on tensor cores. X hi/lo ping-pongs in smem
// (stride 72: fragment loads hit 32 distinct banks); W re-split per layer
// from L2-resident g_wb; sin applied to D fragments in registers.
// 256 threads (8 warps: wm=wid&3 m32, wn=wid>>2 n32).
// ---------------------------------------------------------------------------
#define XS 72
#define XBUF (NG * XS)            // 9216 floats
#define WBUF (DD * XS)            // 4608 floats
#define DEC_SMEM_FLOATS (4 * XBUF + 2 * WBUF + 256)
#define DEC_SMEM_BYTES (DEC_SMEM_FLOATS * 4)

__global__ void __launch_bounds__(256)
k_decode(const float* __restrict__ logP, float* __restrict__ out) {
    extern __shared__ __align__(16) float sm[];
    float* XAh = sm;
    float* XAl = sm + XBUF;
    float* XBh = sm + 2 * XBUF;
    float* XBl = sm + 3 * XBUF;
    float* Wh  = sm + 4 * XBUF;
    float* Wl  = sm + 4 * XBUF + WBUF;
    float* part = sm + 4 * XBUF + 2 * WBUF;

    int b = blockIdx.x;
    int tid = threadIdx.x;
    int lane = tid & 31;
    int wid = tid >> 5;
    int g4 = lane >> 2;
    int t4 = lane & 3;
    int wm = wid & 3;          // m-quarter (32 rows)
    int wn = wid >> 2;         // n-half (32 cols)
    const float* brow = g_wb + (size_t)b * OUTSZ_PAD;

    // ---- first layer (scalar): X0 = sin(30*(xin*W0 + b0)), split hi/lo ----
    {
        int g = tid & (NG - 1);
        int half = tid >> 7;
        float xin = logP[b * NG + g];
        float b0v = brow[12608];
#pragma unroll
        for (int jj = 0; jj < 32; jj++) {
            int j = half * 32 + jj;
            float v = fsin(30.0f * fmaf(xin, brow[OFF_W0 + j], b0v));
            float h = tf32r(v);
            XAh[g * XS + j] = h;
            XAl[g * XS + j] = tf32r(v - h);
        }
    }
    __syncthreads();

#pragma unroll 1
    for (int it = 0; it < 3; it++) {
        // refill W hi/lo from gmem (previous layer's reads done: sync above)
        const float* Wg = brow + it * DD * DD;
        for (int t = tid; t < DD * DD / 4; t += 256) {
            int i = t >> 4, j4 = (t & 15) * 4;
            float4 w = *(const float4*)&Wg[i * DD + j4];
            float hx = tf32r(w.x), hy = tf32r(w.y), hz = tf32r(w.z), hw_ = tf32r(w.w);
            *(float4*)&Wh[i * XS + j4] = make_float4(hx, hy, hz, hw_);
            *(float4*)&Wl[i * XS + j4] =
                make_float4(tf32r(w.x - hx), tf32r(w.y - hy),
                            tf32r(w.z - hz), tf32r(w.w - hw_));
        }
        // bias registers (col-dependent only)
        float be[2][4], bo[2][4];
#pragma unroll
        for (int nf = 0; nf < 2; nf++) {
            // (only nf<... we have 4 n-tiles per warp? n32 = 4 tiles of 8)
        }
        float biasE[4], biasO[4];
#pragma unroll
        for (int nf = 0; nf < 4; nf++) {
            int col = wn * 32 + nf * 8 + 2 * t4;
            biasE[nf] = brow[OFF_B + it * DD + col];
            biasO[nf] = brow[OFF_B + it * DD + col + 1];
        }
        (void)be; (void)bo;
        __syncthreads();

        const float* Xih = (it & 1) ? XBh : XAh;
        const float* Xil = (it & 1) ? XBl : XAl;
        float* Xoh = (it & 1) ? XAh : XBh;
        float* Xol = (it & 1) ? XAl : XBl;

        float4 acc[2][4];
#pragma unroll
        for (int mf = 0; mf < 2; mf++)
#pragma unroll
            for (int nf = 0; nf < 4; nf++)
                acc[mf][nf] = make_float4(biasE[nf], biasO[nf], biasE[nf], biasO[nf]);

#pragma unroll
        for (int k8 = 0; k8 < DD; k8 += 8) {
            uint32_t ah[2][4], al[2][4];
#pragma unroll
            for (int mf = 0; mf < 2; mf++) {
                int m = wm * 32 + mf * 16 + g4;
                ah[mf][0] = __float_as_uint(Xih[m * XS + k8 + t4]);
                ah[mf][1] = __float_as_uint(Xih[(m + 8) * XS + k8 + t4]);
                ah[mf][2] = __float_as_uint(Xih[m * XS + k8 + t4 + 4]);
                ah[mf][3] = __float_as_uint(Xih[(m + 8) * XS + k8 + t4 + 4]);
                al[mf][0] = __float_as_uint(Xil[m * XS + k8 + t4]);
                al[mf][1] = __float_as_uint(Xil[(m + 8) * XS + k8 + t4]);
                al[mf][2] = __float_as_uint(Xil[m * XS + k8 + t4 + 4]);
                al[mf][3] = __float_as_uint(Xil[(m + 8) * XS + k8 + t4 + 4]);
            }
#pragma unroll
            for (int nf = 0; nf < 4; nf++) {
                int n = wn * 32 + nf * 8 + g4;
                uint32_t bh[2], bl[2];
                bh[0] = __float_as_uint(Wh[(k8 + t4) * XS + n]);
                bh[1] = __float_as_uint(Wh[(k8 + t4 + 4) * XS + n]);
                bl[0] = __float_as_uint(Wl[(k8 + t4) * XS + n]);
                bl[1] = __float_as_uint(Wl[(k8 + t4 + 4) * XS + n]);
#pragma unroll
                for (int mf = 0; mf < 2; mf++) {
                    mma_tf32(acc[mf][nf], ah[mf], bh);
                    mma_tf32(acc[mf][nf], ah[mf], bl);
                    mma_tf32(acc[mf][nf], al[mf], bh);
                }
            }
        }

        // sin + split + store to Xnext (c0,c1 -> row g4; c2,c3 -> row g4+8)
#pragma unroll
        for (int mf = 0; mf < 2; mf++) {
            int r0 = wm * 32 + mf * 16 + g4;
#pragma unroll
            for (int nf = 0; nf < 4; nf++) {
                int col = wn * 32 + nf * 8 + 2 * t4;
                float4 a = acc[mf][nf];
                float v0 = fsin(a.x), v1 = fsin(a.y);
                float v2 = fsin(a.z), v3 = fsin(a.w);
                float h0 = tf32r(v0), h1 = tf32r(v1);
                float h2 = tf32r(v2), h3 = tf32r(v3);
                *(u64*)&Xoh[r0 * XS + col] = pack2(h0, h1);
                *(u64*)&Xol[r0 * XS + col] = pack2(tf32r(v0 - h0), tf32r(v1 - h1));
                *(u64*)&Xoh[(r0 + 8) * XS + col] = pack2(h2, h3);
                *(u64*)&Xol[(r0 + 8) * XS + col] = pack2(tf32r(v2 - h2), tf32r(v3 - h3));
            }
        }
        __syncthreads();
    }

    // ---- final layer: out[g] = (X3 . W4) + b4, scaled ----
    // X3 lives in XB (after it=2). 256 threads: (g, half of i-range)
    {
        int g = tid & (NG - 1);
        int half = tid >> 7;
        float s = 0.0f;
#pragma unroll
        for (int ii = 0; ii < 32; ii++) {
            int i = half * 32 + ii;
            float xv = XBh[g * XS + i] + XBl[g * XS + i];
            s = fmaf(xv, brow[OFF_W4 + i], s);
        }
        part[half * NG + g] = s;
    }
    __syncthreads();
    if (tid < NG) {
        float acc = brow[12609] + part[tid] + part[NG + tid];
        out[b * NG + tid] = fmaf(acc, 500.0f, 1500.0f);
    }
}

// ---------------------------------------------------------------------------
extern "C" void kernel_launch(void* const* d_in, const int* in_sizes, int n_in,
                              void* d_out, int out_size) {
    (void)in_sizes; (void)n_in; (void)out_size;
    const float* z    = (const float*)d_in[0];
    const float* logP = (const float*)d_in[1];
    const float* hw0  = (const float*)d_in[2];
    const float* hb0  = (const float*)d_in[3];
    const float* hw1  = (const float*)d_in[4];
    const float* hb1  = (const float*)d_in[5];
    const float* hw2  = (const float*)d_in[6];
    const float* hb2  = (const float*)d_in[7];
    float* out = (float*)d_out;

    float *p_h0, *p_h1, *p_h1t_hi, *p_h1t_lo, *p_wb;
    cudaGetSymbolAddress((void**)&p_h0, g_h0);
    cudaGetSymbolAddress((void**)&p_h1, g_h1);
    cudaGetSymbolAddress((void**)&p_h1t_hi, g_h1t_hi);
    cudaGetSymbolAddress((void**)&p_h1t_lo, g_h1t_lo);
    cudaGetSymbolAddress((void**)&p_wb, g_wb);

    cudaFuncSetAttribute(k_decode, cudaFuncAttributeMaxDynamicSharedMemorySize,
                         DEC_SMEM_BYTES);
    cudaFuncSetAttribute(k_wbgemm, cudaFuncAttributeMaxDynamicSharedMemorySize,
                         WB_SMEM_BYTES);

    // 1) h0
    k_h0<<<NB, HID>>>(z, hw0, hb0);

    // 2) h1 = leaky(h0 @ hw1 + hb1) + transposed tf32 split
    {
        dim3 grid(HID / H1_BN, NB / H1_BM);   // 64 blocks
        gemm_h1<<<grid, 128>>>(p_h0, hw1, hb1, p_h1, p_h1t_hi, p_h1t_lo);
    }

    // 3) wb = h1 @ hw2 + hb2 via mma.sync 3xTF32, permuted store, 132 CTAs
    k_wbgemm<<<(OUTSZ + BNW - 1) / BNW, 256, WB_SMEM_BYTES>>>(
        p_h1t_hi, p_h1t_lo, hw2, hb2, p_wb);

    // 4) decoder on tensor cores
    k_decode<<<NB, 256, DEC_SMEM_BYTES>>>(logP, out);
}

// round 11
// speedup vs baseline: 1.7889x; 1.2248x over previous
#include <cuda_runtime.h>
#include <cuda_fp16.h>
#include <cstdint>

#define LATENT 16
#define HID 512
#define DD 64
#define NB 128
#define NG 128
#define OUTSZ 12610
#define OUTSZ_PAD 12612

// Scratch (device globals — no allocation allowed)
__device__ float g_h0[NB * HID];
__device__ __half g_h1h[NB * HID];     // fp16-hi split of h1, [m][k]
__device__ __half g_h1l[NB * HID];     // fp16-lo split of h1, [m][k]
__device__ float g_wb[NB * OUTSZ_PAD]; // PRE-PERMUTED into decoder layout

typedef unsigned long long u64;

__device__ __forceinline__ u64 pack2(float lo, float hi) {
    u64 r; asm("mov.b64 %0, {%1, %2};" : "=l"(r) : "f"(lo), "f"(hi)); return r;
}
__device__ __forceinline__ void fma2(u64& d, u64 a, u64 b) {
    asm("fma.rn.f32x2 %0, %1, %2, %0;" : "+l"(d) : "l"(a), "l"(b));
}

__device__ __forceinline__ float leaky(float x) { return x > 0.0f ? x : 0.01f * x; }

// fast sin: 2-step Cody-Waite range reduction + MUFU sin (args stay < ~40)
__device__ __forceinline__ float fsin(float x) {
    float k = rintf(x * 0.15915494309189535f);
    x = fmaf(k, -6.28125f, x);
    x = fmaf(k, -1.9353071795864769e-3f, x);
    return __sinf(x);
}

// tf32 round (cvt.rna.tf32.f32 needs a .b32 destination)
__device__ __forceinline__ float tf32r(float x) {
    uint32_t r;
    asm("cvt.rna.tf32.f32 %0, %1;" : "=r"(r) : "f"(x));
    return __uint_as_float(r);
}

// tf32 mma m16n8k8 (decoder)
__device__ __forceinline__ void mma_tf32(float4& c, const uint32_t a[4],
                                         const uint32_t b[2]) {
    asm volatile(
        "mma.sync.aligned.m16n8k8.row.col.f32.tf32.tf32.f32 "
        "{%0,%1,%2,%3}, {%4,%5,%6,%7}, {%8,%9}, {%0,%1,%2,%3};"
        : "+f"(c.x), "+f"(c.y), "+f"(c.z), "+f"(c.w)
        : "r"(a[0]), "r"(a[1]), "r"(a[2]), "r"(a[3]), "r"(b[0]), "r"(b[1]));
}

// fp16 mma m16n8k16 (wb GEMM): 2x MACs/instr vs tf32 k8
__device__ __forceinline__ void mma_f16(float4& c, const uint32_t a[4],
                                        const uint32_t b[2]) {
    asm volatile(
        "mma.sync.aligned.m16n8k16.row.col.f32.f16.f16.f32 "
        "{%0,%1,%2,%3}, {%4,%5,%6,%7}, {%8,%9}, {%0,%1,%2,%3};"
        : "+f"(c.x), "+f"(c.y), "+f"(c.z), "+f"(c.w)
        : "r"(a[0]), "r"(a[1]), "r"(a[2]), "r"(a[3]), "r"(b[0]), "r"(b[1]));
}

// Decoder layout (floats): W1[0,4096) W2[4096,8192) W3[8192,12288) W0[12288,12352)
// b1[12352,12416) b2[12416,12480) b3[12480,12544) W4[12544,12608) b0[12608] b4[12609]
#define OFF_W0 12288
#define OFF_B  12352
#define OFF_W4 12544

__device__ __forceinline__ int perm_wb(int n) {
    if (n < 4161)  return (n < 64) ? 12288 + n : (n == 64 ? 12608 : n - 65);
    if (n < 8321)  return (n < 4225) ? 12352 + (n - 4161) : 4096 + (n - 4225);
    if (n < 12481) return (n < 8385) ? 12416 + (n - 8321) : 8192 + (n - 8385);
    if (n < 12545) return 12480 + (n - 12481);
    return (n < 12609) ? 12544 + (n - 12545) : 12609;
}

// ---------------------------------------------------------------------------
// Kernel 1: h0 = leaky_relu(z @ hw0 + hb0)
// ---------------------------------------------------------------------------
__global__ void k_h0(const float* __restrict__ z, const float* __restrict__ hw0,
                     const float* __restrict__ hb0) {
    int b = blockIdx.x;
    int j = threadIdx.x;
    const float* zr = z + b * LATENT;
    float acc = hb0[j];
#pragma unroll
    for (int k = 0; k < LATENT; k++) acc = fmaf(zr[k], hw0[k * HID + j], acc);
    g_h0[b * HID + j] = leaky(acc);
}

// ---------------------------------------------------------------------------
// FFMA GEMM for h1, prefetch pipeline. Epilogue emits fp16 hi/lo split of
// h1 in [m][k] layout (row-major A operand of the fp16 wb GEMM).
// ---------------------------------------------------------------------------
#define H1_BM 16
#define H1_BN 64
#define H1_BK 16

__global__ void __launch_bounds__(128)
gemm_h1(const float* __restrict__ A, const float* __restrict__ B,
        const float* __restrict__ bias,
        __half* __restrict__ Ch, __half* __restrict__ Cl) {
    constexpr int N = HID, K = HID;
    __shared__ __align__(16) u64 As[H1_BK][H1_BM];
    __shared__ __align__(16) float Bs[H1_BK][H1_BN];

    int tid = threadIdx.x;
    int tx = tid & 15, ty = tid >> 4;
    int m0 = blockIdx.y * H1_BM, n0 = blockIdx.x * H1_BN;

    u64 acc[2][2];
#pragma unroll
    for (int i = 0; i < 2; i++)
#pragma unroll
        for (int j = 0; j < 2; j++) acc[i][j] = pack2(0.0f, 0.0f);

    float4 pa;
    float pb[8];
    int par = tid >> 2, pac4 = tid & 3;
    int pbn = tid & 63, pbk0 = tid >> 6;

    auto ldg_tile = [&](int k0, float4& a4, float pbv[8]) {
        if (tid < 64)
            a4 = *(const float4*)&A[(size_t)(m0 + par) * K + k0 + pac4 * 4];
#pragma unroll
        for (int r = 0; r < 8; r++)
            pbv[r] = B[(size_t)(k0 + pbk0 + r * 2) * N + n0 + pbn];
    };
    auto sts_tile = [&](const float4& a4, const float pbv[8]) {
        if (tid < 64) {
            As[pac4 * 4 + 0][par] = pack2(a4.x, a4.x);
            As[pac4 * 4 + 1][par] = pack2(a4.y, a4.y);
            As[pac4 * 4 + 2][par] = pack2(a4.z, a4.z);
            As[pac4 * 4 + 3][par] = pack2(a4.w, a4.w);
        }
#pragma unroll
        for (int r = 0; r < 8; r++) Bs[pbk0 + r * 2][pbn] = pbv[r];
    };

    ldg_tile(0, pa, pb);
    sts_tile(pa, pb);
    __syncthreads();

    for (int t = 0; t < K / H1_BK; t++) {
        if (t + 1 < K / H1_BK) ldg_tile((t + 1) * H1_BK, pa, pb);
#pragma unroll
        for (int k = 0; k < H1_BK; k++) {
            u64 ra0 = As[k][ty * 2], ra1 = As[k][ty * 2 + 1];
            u64 rb0 = *(const u64*)&Bs[k][tx * 2];
            u64 rb1 = *(const u64*)&Bs[k][tx * 2 + 32];
            fma2(acc[0][0], ra0, rb0); fma2(acc[0][1], ra0, rb1);
            fma2(acc[1][0], ra1, rb0); fma2(acc[1][1], ra1, rb1);
        }
        __syncthreads();
        if (t + 1 < K / H1_BK) {
            sts_tile(pa, pb);
            __syncthreads();
        }
    }

#pragma unroll
    for (int i = 0; i < 2; i++) {
        int m = m0 + ty * 2 + i;
#pragma unroll
        for (int j = 0; j < 2; j++) {
            float lo, hi;
            asm("mov.b64 {%0, %1}, %2;" : "=f"(lo), "=f"(hi) : "l"(acc[i][j]));
            int n = n0 + tx * 2 + j * 32;
            float v0 = leaky(lo + bias[n]);
            float v1 = leaky(hi + bias[n + 1]);
            __half h0 = __float2half_rn(v0), h1 = __float2half_rn(v1);
            __half l0 = __float2half_rn(v0 - __half2float(h0));
            __half l1 = __float2half_rn(v1 - __half2float(h1));
            *(__half2*)&Ch[(size_t)m * HID + n] = __halves2half2(h0, h1);
            *(__half2*)&Cl[(size_t)m * HID + n] = __halves2half2(l0, l1);
        }
    }
}

// ---------------------------------------------------------------------------
// wb GEMM via mma.sync fp16 m16n8k16 (2-split, 3 products = 22-bit mantissa):
//   wb[128,12610] = h1 @ hw2 + bias (permuted store). 132 CTAs x 256 thr.
// CTA tile M=128 x N=96, K-step 32; warp m64 x n24.
// A smem [m][72 fp16] (144B: frag banks 4*g4+t4, conflict-free)
// B smem [n][74 fp16] (148B: store banks 5n, conflict-free; frag ~free)
// ---------------------------------------------------------------------------
#define KT 32
#define BNW 96
#define ASTR 72
#define BSTR 74
#define WB_SMEM_BYTES ((2 * 128 * ASTR + 2 * BNW * BSTR) * 2)

__global__ void __launch_bounds__(256)
k_wbgemm(const __half* __restrict__ Ah_g, const __half* __restrict__ Al_g,
         const float* __restrict__ Bg, const float* __restrict__ bias,
         float* __restrict__ Cout) {
    extern __shared__ __align__(16) __half smh[];
    __half* As_h = smh;
    __half* As_l = smh + 128 * ASTR;
    __half* Bs_h = smh + 2 * 128 * ASTR;
    __half* Bs_l = Bs_h + BNW * BSTR;

    int tid = threadIdx.x;
    int lane = tid & 31;
    int wid = tid >> 5;
    int g4 = lane >> 2;
    int t4 = lane & 3;
    int wm = wid & 1;        // m-half (64 rows)
    int wn = wid >> 1;       // n-quarter (24 cols)
    int n0 = blockIdx.x * BNW;

    int bn = tid % BNW, bkh = tid / BNW;     // B staging: threads < 192
    bool bact = tid < 192;
    bool bok = bact && (n0 + bn) < OUTSZ;

    float4 acc[4][3];
#pragma unroll
    for (int i = 0; i < 4; i++)
#pragma unroll
        for (int j = 0; j < 3; j++) acc[i][j] = make_float4(0.f, 0.f, 0.f, 0.f);

    u64 pah[4], pal[4];
    float pb[16];

    auto ldg_tile = [&](int kt) {
#pragma unroll
        for (int i = 0; i < 4; i++) {
            int idx = tid + i * 256;          // 1024 u64 slots (128 rows x 8)
            int m = idx >> 3, j = idx & 7;
            pah[i] = *(const u64*)&Ah_g[(size_t)m * HID + kt + j * 4];
            pal[i] = *(const u64*)&Al_g[(size_t)m * HID + kt + j * 4];
        }
        if (bact) {
            const float* bp = Bg + (size_t)(kt + bkh * 16) * OUTSZ + n0 + bn;
#pragma unroll
            for (int j = 0; j < 16; j++)
                pb[j] = bok ? bp[(size_t)j * OUTSZ] : 0.0f;
        }
    };
    auto sts_tile = [&]() {
#pragma unroll
        for (int i = 0; i < 4; i++) {
            int idx = tid + i * 256;
            int m = idx >> 3, j = idx & 7;
            *(u64*)&As_h[m * ASTR + j * 4] = pah[i];
            *(u64*)&As_l[m * ASTR + j * 4] = pal[i];
        }
        if (bact) {
#pragma unroll
            for (int j = 0; j < 8; j++) {
                float v0 = pb[2 * j], v1 = pb[2 * j + 1];
                __half h0 = __float2half_rn(v0), h1 = __float2half_rn(v1);
                __half l0 = __float2half_rn(v0 - __half2float(h0));
                __half l1 = __float2half_rn(v1 - __half2float(h1));
                *(__half2*)&Bs_h[bn * BSTR + bkh * 16 + 2 * j] = __halves2half2(h0, h1);
                *(__half2*)&Bs_l[bn * BSTR + bkh * 16 + 2 * j] = __halves2half2(l0, l1);
            }
        }
    };

    ldg_tile(0);
    sts_tile();
    __syncthreads();

    for (int t = 0; t < HID / KT; t++) {
        if (t + 1 < HID / KT) ldg_tile((t + 1) * KT);

#pragma unroll
        for (int ks = 0; ks < KT; ks += 16) {
            uint32_t ah[4][4], al[4][4];
#pragma unroll
            for (int mf = 0; mf < 4; mf++) {
                int m = wm * 64 + mf * 16 + g4;
                ah[mf][0] = *(const uint32_t*)&As_h[m * ASTR + ks + 2 * t4];
                ah[mf][1] = *(const uint32_t*)&As_h[(m + 8) * ASTR + ks + 2 * t4];
                ah[mf][2] = *(const uint32_t*)&As_h[m * ASTR + ks + 2 * t4 + 8];
                ah[mf][3] = *(const uint32_t*)&As_h[(m + 8) * ASTR + ks + 2 * t4 + 8];
                al[mf][0] = *(const uint32_t*)&As_l[m * ASTR + ks + 2 * t4];
                al[mf][1] = *(const uint32_t*)&As_l[(m + 8) * ASTR + ks + 2 * t4];
                al[mf][2] = *(const uint32_t*)&As_l[m * ASTR + ks + 2 * t4 + 8];
                al[mf][3] = *(const uint32_t*)&As_l[(m + 8) * ASTR + ks + 2 * t4 + 8];
            }
#pragma unroll
            for (int nf = 0; nf < 3; nf++) {
                int n = wn * 24 + nf * 8 + g4;
                uint32_t bh[2], bl[2];
                bh[0] = *(const uint32_t*)&Bs_h[n * BSTR + ks + 2 * t4];
                bh[1] = *(const uint32_t*)&Bs_h[n * BSTR + ks + 2 * t4 + 8];
                bl[0] = *(const uint32_t*)&Bs_l[n * BSTR + ks + 2 * t4];
                bl[1] = *(const uint32_t*)&Bs_l[n * BSTR + ks + 2 * t4 + 8];
#pragma unroll
                for (int mf = 0; mf < 4; mf++) {
                    mma_f16(acc[mf][nf], ah[mf], bh);
                    mma_f16(acc[mf][nf], ah[mf], bl);
                    mma_f16(acc[mf][nf], al[mf], bh);
                }
            }
        }
        __syncthreads();
        if (t + 1 < HID / KT) {
            sts_tile();
            __syncthreads();
        }
    }

    // epilogue: bias + permuted scatter
#pragma unroll
    for (int mf = 0; mf < 4; mf++) {
        int m = wm * 64 + mf * 16 + g4;
#pragma unroll
        for (int nf = 0; nf < 3; nf++) {
            int n = n0 + wn * 24 + nf * 8 + t4 * 2;
            if (n < OUTSZ) {
                Cout[(size_t)m * OUTSZ_PAD + perm_wb(n)] = acc[mf][nf].x + bias[n];
                Cout[(size_t)(m + 8) * OUTSZ_PAD + perm_wb(n)] = acc[mf][nf].z + bias[n];
            }
            if (n + 1 < OUTSZ) {
                Cout[(size_t)m * OUTSZ_PAD + perm_wb(n + 1)] = acc[mf][nf].y + bias[n + 1];
                Cout[(size_t)(m + 8) * OUTSZ_PAD + perm_wb(n + 1)] = acc[mf][nf].w + bias[n + 1];
            }
        }
    }
}

// ---------------------------------------------------------------------------
// Decoder via mma.sync tf32 (2-split), 512 threads (16 warps: wm 0..7 m16,
// wn 0..1 n32). X stride 68 (A-frag banks 4g4+t4, conflict-free);
// W stride 72 (B-frag banks 8t4+g4, conflict-free).
// ---------------------------------------------------------------------------
#define XSX 68
#define XSW 72
#define XBUF (NG * XSX)           // 8704 floats
#define WBUF (DD * XSW)           // 4608 floats
#define DEC_SMEM_FLOATS (4 * XBUF + 2 * WBUF + 512)
#define DEC_SMEM_BYTES (DEC_SMEM_FLOATS * 4)

__global__ void __launch_bounds__(512)
k_decode(const float* __restrict__ logP, float* __restrict__ out) {
    extern __shared__ __align__(16) float sm[];
    float* XAh = sm;
    float* XAl = sm + XBUF;
    float* XBh = sm + 2 * XBUF;
    float* XBl = sm + 3 * XBUF;
    float* Wh  = sm + 4 * XBUF;
    float* Wl  = sm + 4 * XBUF + WBUF;
    float* part = sm + 4 * XBUF + 2 * WBUF;

    int b = blockIdx.x;
    int tid = threadIdx.x;
    int lane = tid & 31;
    int wid = tid >> 5;
    int g4 = lane >> 2;
    int t4 = lane & 3;
    int wm = wid & 7;          // m-sixteenth (16 rows)
    int wn = wid >> 3;         // n-half (32 cols)
    const float* brow = g_wb + (size_t)b * OUTSZ_PAD;

    // ---- first layer (scalar): X0 = sin(30*(xin*W0 + b0)), split hi/lo ----
    {
        int g = tid & (NG - 1);
        int q = tid >> 7;                    // 0..3
        float xin = logP[b * NG + g];
        float b0v = brow[12608];
#pragma unroll
        for (int jj = 0; jj < 16; jj++) {
            int j = q * 16 + jj;
            float v = fsin(30.0f * fmaf(xin, brow[OFF_W0 + j], b0v));
            float h = tf32r(v);
            XAh[g * XSX + j] = h;
            XAl[g * XSX + j] = tf32r(v - h);
        }
    }
    __syncthreads();

#pragma unroll 1
    for (int it = 0; it < 3; it++) {
        // W hi/lo refill from L2-resident g_wb
        const float* Wg = brow + it * DD * DD;
#pragma unroll
        for (int r = 0; r < 2; r++) {
            int t = tid + r * 512;
            int i = t >> 4, j4 = (t & 15) * 4;
            float4 w = *(const float4*)&Wg[i * DD + j4];
            float hx = tf32r(w.x), hy = tf32r(w.y), hz = tf32r(w.z), hw_ = tf32r(w.w);
            *(float4*)&Wh[i * XSW + j4] = make_float4(hx, hy, hz, hw_);
            *(float4*)&Wl[i * XSW + j4] =
                make_float4(tf32r(w.x - hx), tf32r(w.y - hy),
                            tf32r(w.z - hz), tf32r(w.w - hw_));
        }
        float biasE[4], biasO[4];
#pragma unroll
        for (int nf = 0; nf < 4; nf++) {
            int col = wn * 32 + nf * 8 + 2 * t4;
            biasE[nf] = brow[OFF_B + it * DD + col];
            biasO[nf] = brow[OFF_B + it * DD + col + 1];
        }
        __syncthreads();

        const float* Xih = (it & 1) ? XBh : XAh;
        const float* Xil = (it & 1) ? XBl : XAl;
        float* Xoh = (it & 1) ? XAh : XBh;
        float* Xol = (it & 1) ? XAl : XBl;

        float4 acc[4];
#pragma unroll
        for (int nf = 0; nf < 4; nf++)
            acc[nf] = make_float4(biasE[nf], biasO[nf], biasE[nf], biasO[nf]);

        int m = wm * 16 + g4;
#pragma unroll
        for (int k8 = 0; k8 < DD; k8 += 8) {
            uint32_t ah[4], al[4];
            ah[0] = __float_as_uint(Xih[m * XSX + k8 + t4]);
            ah[1] = __float_as_uint(Xih[(m + 8) * XSX + k8 + t4]);
            ah[2] = __float_as_uint(Xih[m * XSX + k8 + t4 + 4]);
            ah[3] = __float_as_uint(Xih[(m + 8) * XSX + k8 + t4 + 4]);
            al[0] = __float_as_uint(Xil[m * XSX + k8 + t4]);
            al[1] = __float_as_uint(Xil[(m + 8) * XSX + k8 + t4]);
            al[2] = __float_as_uint(Xil[m * XSX + k8 + t4 + 4]);
            al[3] = __float_as_uint(Xil[(m + 8) * XSX + k8 + t4 + 4]);
#pragma unroll
            for (int nf = 0; nf < 4; nf++) {
                int n = wn * 32 + nf * 8 + g4;
                uint32_t bh[2], bl[2];
                bh[0] = __float_as_uint(Wh[(k8 + t4) * XSW + n]);
                bh[1] = __float_as_uint(Wh[(k8 + t4 + 4) * XSW + n]);
                bl[0] = __float_as_uint(Wl[(k8 + t4) * XSW + n]);
                bl[1] = __float_as_uint(Wl[(k8 + t4 + 4) * XSW + n]);
                mma_tf32(acc[nf], ah, bh);
                mma_tf32(acc[nf], ah, bl);
                mma_tf32(acc[nf], al, bh);
            }
        }

        // sin + split + store (c0,c1 -> row m; c2,c3 -> row m+8)
#pragma unroll
        for (int nf = 0; nf < 4; nf++) {
            int col = wn * 32 + nf * 8 + 2 * t4;
            float4 a = acc[nf];
            float v0 = fsin(a.x), v1 = fsin(a.y);
            float v2 = fsin(a.z), v3 = fsin(a.w);
            float h0 = tf32r(v0), h1 = tf32r(v1);
            float h2 = tf32r(v2), h3 = tf32r(v3);
            *(u64*)&Xoh[m * XSX + col] = pack2(h0, h1);
            *(u64*)&Xol[m * XSX + col] = pack2(tf32r(v0 - h0), tf32r(v1 - h1));
            *(u64*)&Xoh[(m + 8) * XSX + col] = pack2(h2, h3);
            *(u64*)&Xol[(m + 8) * XSX + col] = pack2(tf32r(v2 - h2), tf32r(v3 - h3));
        }
        __syncthreads();
    }

    // ---- final layer: out[g] = (X3 . W4) + b4 (X3 in XB after it=2) ----
    {
        int g = tid & (NG - 1);
        int q = tid >> 7;
        float s = 0.0f;
#pragma unroll
        for (int ii = 0; ii < 16; ii++) {
            int i = q * 16 + ii;
            float xv = XBh[g * XSX + i] + XBl[g * XSX + i];
            s = fmaf(xv, brow[OFF_W4 + i], s);
        }
        part[q * NG + g] = s;
    }
    __syncthreads();
    if (tid < NG) {
        float acc = brow[12609] + part[tid] + part[NG + tid]
                  + part[2 * NG + tid] + part[3 * NG + tid];
        out[b * NG + tid] = fmaf(acc, 500.0f, 1500.0f);
    }
}

// ---------------------------------------------------------------------------
extern "C" void kernel_launch(void* const* d_in, const int* in_sizes, int n_in,
                              void* d_out, int out_size) {
    (void)in_sizes; (void)n_in; (void)out_size;
    const float* z    = (const float*)d_in[0];
    const float* logP = (const float*)d_in[1];
    const float* hw0  = (const float*)d_in[2];
    const float* hb0  = (const float*)d_in[3];
    const float* hw1  = (const float*)d_in[4];
    const float* hb1  = (const float*)d_in[5];
    const float* hw2  = (const float*)d_in[6];
    const float* hb2  = (const float*)d_in[7];
    float* out = (float*)d_out;

    float *p_h0, *p_wb;
    __half *p_h1h, *p_h1l;
    cudaGetSymbolAddress((void**)&p_h0, g_h0);
    cudaGetSymbolAddress((void**)&p_h1h, g_h1h);
    cudaGetSymbolAddress((void**)&p_h1l, g_h1l);
    cudaGetSymbolAddress((void**)&p_wb, g_wb);

    cudaFuncSetAttribute(k_decode, cudaFuncAttributeMaxDynamicSharedMemorySize,
                         DEC_SMEM_BYTES);
    cudaFuncSetAttribute(k_wbgemm, cudaFuncAttributeMaxDynamicSharedMemorySize,
                         WB_SMEM_BYTES);

    // 1) h0
    k_h0<<<NB, HID>>>(z, hw0, hb0);

    // 2) h1 = leaky(h0 @ hw1 + hb1), fp16 hi/lo split output
    {
        dim3 grid(HID / H1_BN, NB / H1_BM);   // 64 blocks
        gemm_h1<<<grid, 128>>>(p_h0, hw1, hb1, p_h1h, p_h1l);
    }

    // 3) wb = h1 @ hw2 + hb2 via fp16 mma (2-split), permuted store, 132 CTAs
    k_wbgemm<<<(OUTSZ + BNW - 1) / BNW, 256, WB_SMEM_BYTES>>>(
        p_h1h, p_h1l, hw2, hb2, p_wb);

    // 4) decoder on tensor cores
    k_decode<<<NB, 512, DEC_SMEM_BYTES>>>(logP, out);
}